// round 8
// baseline (speedup 1.0000x reference)
#include <cuda_runtime.h>
#include <math.h>
#include <stdint.h>

constexpr int B_  = 16;
constexpr int H_  = 1024;
constexpr int CO_ = 512;
constexpr int NV_ = 2048;
constexpr int NQ_ = 2048;

constexpr size_t SZ_Q  = (size_t)B_ * NQ_ * H_;
constexpr size_t SZ_V  = (size_t)B_ * H_ * NV_;
constexpr size_t SZ_NC = (size_t)B_ * NQ_ * CO_;
constexpr size_t SZ_HC = (size_t)B_ * H_ * CO_;
constexpr size_t SZ_W  = (size_t)H_ * H_;
constexpr size_t SZ_WC = (size_t)H_ * CO_;

// -------- scratch (device globals; lifetimes aliased to cut footprint) -----
__device__ float g_Qh [SZ_Q],  g_Ql [SZ_Q];     // also host MvT / MqT after G3
__device__ float g_Qth[SZ_Q],  g_Qtl[SZ_Q];
__device__ float g_Vh [SZ_V],  g_Vl [SZ_V];
__device__ float g_Vth[SZ_V],  g_Vtl[SZ_V];
__device__ float g_Wbh[SZ_W],  g_Wbl[SZ_W], g_Wbth[SZ_W], g_Wbtl[SZ_W];
__device__ float g_WqTh[SZ_WC], g_WqTl[SZ_WC], g_WvTh[SZ_WC], g_WvTl[SZ_WC];
__device__ float g_T1 [SZ_NC], g_T1h[SZ_NC], g_T1l[SZ_NC];
__device__ float g_T2 [SZ_NC], g_T2h[SZ_NC], g_T2l[SZ_NC];
__device__ float g_PvTh[SZ_HC], g_PvTl[SZ_HC];  // also PqT (G6..G7)
__device__ float g_RvTh[SZ_HC], g_RvTl[SZ_HC];  // also RqT (G7..G8)
__device__ float g_logv[(size_t)B_ * NV_], g_logq[(size_t)B_ * NQ_];
__device__ float g_part[(size_t)B_ * 16 * H_];

__device__ __forceinline__ uint32_t smem_u32(const void* p) {
    uint32_t a;
    asm("{ .reg .u64 t; cvta.to.shared.u64 t, %1; cvt.u32.u64 %0, t; }" : "=r"(a) : "l"(p));
    return a;
}
#define CPA16(dst, src) \
    asm volatile("cp.async.cg.shared.global [%0], [%1], 16;" :: "r"(dst), "l"(src))
#define CP_COMMIT() asm volatile("cp.async.commit_group;" ::: "memory")
#define CP_WAIT1()  asm volatile("cp.async.wait_group 1;" ::: "memory")

__device__ __forceinline__ void split_tf32(float x, float& h, float& l) {
    uint32_t u;
    asm("cvt.rna.tf32.f32 %0, %1;" : "=r"(u) : "f"(x));
    h = __uint_as_float(u);
    const float lf = x - h;
    asm("cvt.rna.tf32.f32 %0, %1;" : "=r"(u) : "f"(lf));
    l = __uint_as_float(u);
}
__device__ __forceinline__ void mma8(float* c, const uint32_t* a, const uint32_t* b) {
    asm volatile(
        "mma.sync.aligned.m16n8k8.row.col.f32.tf32.tf32.f32 "
        "{%0,%1,%2,%3}, {%4,%5,%6,%7}, {%8,%9}, {%0,%1,%2,%3};"
        : "+f"(c[0]), "+f"(c[1]), "+f"(c[2]), "+f"(c[3])
        : "r"(a[0]), "r"(a[1]), "r"(a[2]), "r"(a[3]), "r"(b[0]), "r"(b[1]));
}

// ---------------------------------------------------------------------------
// C[M,512] = A^T*B via tf32 mma, pre-split operands (hi/lo in global).
// A[K,M] k-major (lda), B[K,512]. Block 128x128, 8 warps 64x32, K-slab 16,
// 3-stage cp.async. SROW=136 -> conflict-free fragment LDS.
// EPI bit0: write C fp32; bit1: write Ch/Cl split. grid=(4, M/128, batch)
// ---------------------------------------------------------------------------
constexpr int SROW = 136;
constexpr int TILE_F = 16 * SROW;
constexpr int STG_F = 4 * TILE_F;
constexpr int SMEM_MMA = 3 * STG_F * 4;    // 104448 B

template <int EPI>
__global__ __launch_bounds__(256, 2)
void gemm_mma(const float* __restrict__ Ah, const float* __restrict__ Al, int lda, size_t sA,
              const float* __restrict__ Bh, const float* __restrict__ Bl, size_t sB,
              float* __restrict__ C, float* __restrict__ Ch, float* __restrict__ Cl,
              size_t sC, int K)
{
    extern __shared__ __align__(16) float sm[];
    const int tid = threadIdx.x;
    const int bx = blockIdx.x, by = blockIdx.y, bz = blockIdx.z;

    const float* gAh = Ah + (size_t)bz * sA + by * 128;
    const float* gAl = Al + (size_t)bz * sA + by * 128;
    const float* gBh = Bh + (size_t)bz * sB + bx * 128;
    const float* gBl = Bl + (size_t)bz * sB + bx * 128;

    const int lane = tid & 31, w = tid >> 5;
    const int g = lane >> 2, t = lane & 3;
    const int rbase = (w & 1) * 64;
    const int cbase = (w >> 1) * 32;

    const uint32_t smb = smem_u32(sm);
    const int srow = tid >> 4;          // 0..15
    const int scol = (tid & 15) * 8;

    float c[4][4][4];
#pragma unroll
    for (int i = 0; i < 4; ++i)
#pragma unroll
        for (int j = 0; j < 4; ++j)
#pragma unroll
            for (int k = 0; k < 4; ++k) c[i][j][k] = 0.f;

    const int T = K >> 4;
    const uint32_t doff = (uint32_t)(srow * SROW + scol) * 4;

#define STAGE_LOADS(sidx, k0) do {                                              \
    const uint32_t base_ = smb + (uint32_t)(sidx) * (STG_F * 4);                \
    const size_t kr_ = (size_t)((k0) + srow);                                   \
    CPA16(base_ + doff,                    gAh + kr_ * lda + scol);             \
    CPA16(base_ + doff + 16,               gAh + kr_ * lda + scol + 4);         \
    CPA16(base_ + TILE_F*4 + doff,         gAl + kr_ * lda + scol);             \
    CPA16(base_ + TILE_F*4 + doff + 16,    gAl + kr_ * lda + scol + 4);         \
    CPA16(base_ + 2*TILE_F*4 + doff,       gBh + kr_ * 512 + scol);             \
    CPA16(base_ + 2*TILE_F*4 + doff + 16,  gBh + kr_ * 512 + scol + 4);         \
    CPA16(base_ + 3*TILE_F*4 + doff,       gBl + kr_ * 512 + scol);             \
    CPA16(base_ + 3*TILE_F*4 + doff + 16,  gBl + kr_ * 512 + scol + 4);         \
} while (0)

#pragma unroll
    for (int s = 0; s < 3; ++s) {
        STAGE_LOADS(s, s * 16);
        CP_COMMIT();
    }

    int buf = 0;
    for (int tt = 0; tt < T; ++tt) {
        CP_WAIT1();
        __syncthreads();

        const uint32_t* Ahs = reinterpret_cast<const uint32_t*>(sm + buf * STG_F);
        const uint32_t* Als = Ahs + TILE_F;
        const uint32_t* Bhs = Als + TILE_F;
        const uint32_t* Bls = Bhs + TILE_F;
#pragma unroll
        for (int ks = 0; ks < 2; ++ks) {
            const int kr = ks * 8 + t;
            const uint32_t* aph = Ahs + kr * SROW;
            const uint32_t* apl = Als + kr * SROW;
            const uint32_t* bph = Bhs + kr * SROW;
            const uint32_t* bpl = Bls + kr * SROW;
            uint32_t ah[4][4], al[4][4], bh[4][2], bl[4][2];
#pragma unroll
            for (int i = 0; i < 4; ++i) {
                const int m = rbase + i * 16 + g;
                ah[i][0] = aph[m];            al[i][0] = apl[m];
                ah[i][1] = aph[m + 8];        al[i][1] = apl[m + 8];
                ah[i][2] = aph[4*SROW + m];   al[i][2] = apl[4*SROW + m];
                ah[i][3] = aph[4*SROW + m+8]; al[i][3] = apl[4*SROW + m+8];
            }
#pragma unroll
            for (int j = 0; j < 4; ++j) {
                const int n = cbase + j * 8 + g;
                bh[j][0] = bph[n];            bl[j][0] = bpl[n];
                bh[j][1] = bph[4*SROW + n];   bl[j][1] = bpl[4*SROW + n];
            }
#pragma unroll
            for (int i = 0; i < 4; ++i)
#pragma unroll
                for (int j = 0; j < 4; ++j) {
                    mma8(c[i][j], ah[i], bl[j]);
                    mma8(c[i][j], al[i], bh[j]);
                    mma8(c[i][j], ah[i], bh[j]);
                }
        }
        __syncthreads();

        if (tt + 3 < T) STAGE_LOADS(buf, (tt + 3) * 16);
        CP_COMMIT();
        buf = (buf == 2) ? 0 : buf + 1;
    }
#undef STAGE_LOADS

    const size_t coff = (size_t)bz * sC + (size_t)(by * 128) * 512 + bx * 128;
#pragma unroll
    for (int i = 0; i < 4; ++i) {
        const int r0 = rbase + i * 16 + g;
#pragma unroll
        for (int j = 0; j < 4; ++j) {
            const int cc = cbase + j * 8 + 2 * t;
            const size_t o0 = coff + (size_t)r0 * 512 + cc;
            const size_t o1 = coff + (size_t)(r0 + 8) * 512 + cc;
            if (EPI & 1) {
                *reinterpret_cast<float2*>(C + o0) = make_float2(c[i][j][0], c[i][j][1]);
                *reinterpret_cast<float2*>(C + o1) = make_float2(c[i][j][2], c[i][j][3]);
            }
            if (EPI & 2) {
                float h0, l0, h1, l1;
                split_tf32(c[i][j][0], h0, l0); split_tf32(c[i][j][1], h1, l1);
                *reinterpret_cast<float2*>(Ch + o0) = make_float2(h0, h1);
                *reinterpret_cast<float2*>(Cl + o0) = make_float2(l0, l1);
                split_tf32(c[i][j][2], h0, l0); split_tf32(c[i][j][3], h1, l1);
                *reinterpret_cast<float2*>(Ch + o1) = make_float2(h0, h1);
                *reinterpret_cast<float2*>(Cl + o1) = make_float2(l0, l1);
            }
        }
    }
}

// ---------------- elementwise split: src -> (hi, lo) ----------------------
__global__ void split_k(const float4* __restrict__ src, float4* __restrict__ h4,
                        float4* __restrict__ l4, int n4)
{
    const int i = blockIdx.x * 256 + threadIdx.x;
    if (i >= n4) return;
    const float4 v = src[i];
    float4 h, l;
    split_tf32(v.x, h.x, l.x); split_tf32(v.y, h.y, l.y);
    split_tf32(v.z, h.z, l.z); split_tf32(v.w, h.w, l.w);
    h4[i] = h; l4[i] = l;
}

// ------- transpose + split: src[bz][R][Cc] -> (hi, lo) at [bz][Cc][R] ------
__global__ void transpose_split_k(const float* __restrict__ src,
                                  float* __restrict__ dh, float* __restrict__ dl,
                                  int R, int Cc)
{
    __shared__ float tile[32][33];
    const size_t off = (size_t)blockIdx.z * R * Cc;
    const float* s = src + off;
    const int x = blockIdx.x * 32 + threadIdx.x;
    for (int j = threadIdx.y; j < 32; j += 8)
        tile[j][threadIdx.x] = s[(size_t)(blockIdx.y * 32 + j) * Cc + x];
    __syncthreads();
    const int x2 = blockIdx.y * 32 + threadIdx.x;
    for (int j = threadIdx.y; j < 32; j += 8) {
        const float v = tile[threadIdx.x][j];
        const size_t o = off + (size_t)(blockIdx.x * 32 + j) * R + x2;
        float h, l;
        split_tf32(v, h, l);
        dh[o] = h; dl[o] = l;
    }
}

// -------- logits[b,n] = sum_c w[c]*tanh(X[b,n,c]+Y[b,n,c]); warp per n -----
__global__ void logits_t(const float* __restrict__ X, const float* __restrict__ Y,
                         const float* __restrict__ w, float* __restrict__ lg, int Ncol)
{
    const int b = blockIdx.y;
    const int n = blockIdx.x * 8 + (threadIdx.x >> 5);
    const int lane = threadIdx.x & 31;
    const float* xp = X + ((size_t)b * Ncol + n) * CO_;
    const float* yp = Y + ((size_t)b * Ncol + n) * CO_;
    float acc = 0.f;
#pragma unroll 4
    for (int c = lane; c < CO_; c += 32)
        acc += w[c] * tanhf(xp[c] + yp[c]);
#pragma unroll
    for (int off = 16; off > 0; off >>= 1)
        acc += __shfl_down_sync(0xffffffffu, acc, off);
    if (lane == 0) lg[(size_t)b * Ncol + n] = acc;
}

// ---------------- softmax over Ncol per batch; grid=B, block=256 -----------
__global__ void softmax_kernel(const float* __restrict__ lg, float* __restrict__ outp, int Ncol)
{
    __shared__ float buf[2048];
    __shared__ float red[256];
    const int b = blockIdx.x, tid = threadIdx.x;
    const float* x = lg + (size_t)b * Ncol;
    float mx = -INFINITY;
    for (int i = tid; i < Ncol; i += 256) { float v = x[i]; buf[i] = v; mx = fmaxf(mx, v); }
    red[tid] = mx; __syncthreads();
    for (int s = 128; s > 0; s >>= 1) { if (tid < s) red[tid] = fmaxf(red[tid], red[tid + s]); __syncthreads(); }
    mx = red[0]; __syncthreads();
    float sm = 0.f;
    for (int i = tid; i < Ncol; i += 256) { float e = expf(buf[i] - mx); buf[i] = e; sm += e; }
    red[tid] = sm; __syncthreads();
    for (int s = 128; s > 0; s >>= 1) { if (tid < s) red[tid] += red[tid + s]; __syncthreads(); }
    const float inv = 1.f / red[0];
    for (int i = tid; i < Ncol; i += 256) outp[(size_t)b * Ncol + i] = buf[i] * inv;
}

// ------ out[b,h] = sum_n a[b,n]*X[b,h,n]; warp per h. grid=(H/8,B) ---------
__global__ void wdot_kernel(const float* __restrict__ a, const float* __restrict__ X,
                            float* __restrict__ outv, int Ncol)
{
    const int b = blockIdx.y;
    const int h = blockIdx.x * 8 + (threadIdx.x >> 5);
    const int lane = threadIdx.x & 31;
    const float* row = X + ((size_t)b * H_ + h) * Ncol;
    const float* av = a + (size_t)b * Ncol;
    float acc = 0.f;
    for (int i = lane; i < Ncol; i += 32) acc += av[i] * row[i];
#pragma unroll
    for (int off = 16; off > 0; off >>= 1) acc += __shfl_down_sync(0xffffffffu, acc, off);
    if (lane == 0) outv[(size_t)b * H_ + h] = acc;
}

// ----- q[b,h] = sum_q a[b,q]*Q[b,q,h]; deterministic 2-stage reduction -----
__global__ void aq_Q_partial(const float* __restrict__ a, const float* __restrict__ Q,
                             float* __restrict__ part)
{
    const int b = blockIdx.y, j = blockIdx.x;
    const int h = threadIdx.x;
    const float* aq = a + (size_t)b * NQ_;
    float acc = 0.f;
    const int q0 = j * (NQ_ / 16);
    for (int q = q0; q < q0 + NQ_ / 16; ++q)
        acc += aq[q] * Q[((size_t)b * NQ_ + q) * H_ + h];
    part[((size_t)b * 16 + j) * H_ + h] = acc;
}
__global__ void aq_Q_reduce(const float* __restrict__ part, float* __restrict__ outq)
{
    const int b = blockIdx.x;
    const int h = threadIdx.x;
    float acc = 0.f;
#pragma unroll
    for (int j = 0; j < 16; ++j)
        acc += part[((size_t)b * 16 + j) * H_ + h];
    outq[(size_t)b * H_ + h] = acc;
}

// ---------------------------------------------------------------------------
extern "C" void kernel_launch(void* const* d_in, const int* in_sizes, int n_in,
                              void* d_out, int out_size)
{
    const float* V    = (const float*)d_in[0];  // [B, H, NV]
    const float* Q    = (const float*)d_in[1];  // [B, NQ, H]
    const float* W_b  = (const float*)d_in[2];  // [H, H]
    const float* W_v  = (const float*)d_in[3];  // [CO, H]
    const float* W_q  = (const float*)d_in[4];  // [CO, H]
    const float* w_hv = (const float*)d_in[5];
    const float* w_hq = (const float*)d_in[6];
    float* out = (float*)d_out;

#define SYM(p, s) float* p; cudaGetSymbolAddress((void**)&p, s)
    SYM(Qh, g_Qh);   SYM(Ql, g_Ql);
    SYM(Qth, g_Qth); SYM(Qtl, g_Qtl);
    SYM(Vh, g_Vh);   SYM(Vl, g_Vl);
    SYM(Vth, g_Vth); SYM(Vtl, g_Vtl);
    SYM(Wbh, g_Wbh); SYM(Wbl, g_Wbl); SYM(Wbth, g_Wbth); SYM(Wbtl, g_Wbtl);
    SYM(WqTh, g_WqTh); SYM(WqTl, g_WqTl); SYM(WvTh, g_WvTh); SYM(WvTl, g_WvTl);
    SYM(T1, g_T1);   SYM(T1h, g_T1h); SYM(T1l, g_T1l);
    SYM(T2, g_T2);   SYM(T2h, g_T2h); SYM(T2l, g_T2l);
    SYM(PvTh, g_PvTh); SYM(PvTl, g_PvTl); SYM(RvTh, g_RvTh); SYM(RvTl, g_RvTl);
    SYM(logv, g_logv); SYM(logq, g_logq); SYM(part, g_part);
#undef SYM
    // lifetime aliases (sequential stream; no overlap within any launch)
    float* PqTh = PvTh;  float* PqTl = PvTl;   // PvT dead after G4
    float* RqTh = RvTh;  float* RqTl = RvTl;   // RvT dead after G5
    float* MvT  = Qh;                          // Qh dead after G3
    float* MqT  = Ql;                          // Ql dead after G3

    cudaFuncSetAttribute(gemm_mma<1>, cudaFuncAttributeMaxDynamicSharedMemorySize, SMEM_MMA);
    cudaFuncSetAttribute(gemm_mma<2>, cudaFuncAttributeMaxDynamicSharedMemorySize, SMEM_MMA);
    cudaFuncSetAttribute(gemm_mma<3>, cudaFuncAttributeMaxDynamicSharedMemorySize, SMEM_MMA);

    const size_t sQ  = (size_t)NQ_ * H_;
    const size_t sV  = (size_t)H_ * NV_;
    const size_t sNC = (size_t)NQ_ * CO_;
    const size_t sHC = (size_t)H_ * CO_;

    // pre-pass: splits + transpose-splits
    split_k<<<(int)(SZ_Q/4/256), 256>>>((const float4*)Q, (float4*)Qh, (float4*)Ql, (int)(SZ_Q/4));
    split_k<<<(int)(SZ_V/4/256), 256>>>((const float4*)V, (float4*)Vh, (float4*)Vl, (int)(SZ_V/4));
    split_k<<<(int)(SZ_W/4/256), 256>>>((const float4*)W_b, (float4*)Wbh, (float4*)Wbl, (int)(SZ_W/4));
    transpose_split_k<<<dim3(H_/32, NQ_/32, B_), dim3(32, 8)>>>(Q, Qth, Qtl, NQ_, H_);
    transpose_split_k<<<dim3(NV_/32, H_/32, B_), dim3(32, 8)>>>(V, Vth, Vtl, H_, NV_);
    transpose_split_k<<<dim3(H_/32, H_/32, 1),  dim3(32, 8)>>>(W_b, Wbth, Wbtl, H_, H_);
    transpose_split_k<<<dim3(H_/32, CO_/32, 1), dim3(32, 8)>>>(W_q, WqTh, WqTl, CO_, H_);
    transpose_split_k<<<dim3(H_/32, CO_/32, 1), dim3(32, 8)>>>(W_v, WvTh, WvTl, CO_, H_);

    // 1. T1 = Qt^T·WqT   [NQ,CO] K=H   (fp32 + split)
    gemm_mma<3><<<dim3(4, NQ_/128, B_), 256, SMEM_MMA>>>(Qth, Qtl, NQ_, sQ, WqTh, WqTl, 0, T1, T1h, T1l, sNC, H_);
    // 2. T2 = V^T·WvT    [NV,CO] K=H
    gemm_mma<3><<<dim3(4, NV_/128, B_), 256, SMEM_MMA>>>(Vh, Vl, NV_, sV, WvTh, WvTl, 0, T2, T2h, T2l, sNC, H_);
    // 3. PvT = Q^T·T1    [H,CO]  K=NQ  (split only)
    gemm_mma<2><<<dim3(4, H_/128, B_), 256, SMEM_MMA>>>(Qh, Ql, H_, sQ, T1h, T1l, sNC, nullptr, PvTh, PvTl, sHC, NQ_);
    // 4. RvT = W_b^T·PvT [H,CO]  K=H
    gemm_mma<2><<<dim3(4, H_/128, B_), 256, SMEM_MMA>>>(Wbh, Wbl, H_, 0, PvTh, PvTl, sHC, nullptr, RvTh, RvTl, sHC, H_);
    // 5. MvT = V^T·RvT   [NV,CO] K=H   (fp32 only)
    gemm_mma<1><<<dim3(4, NV_/128, B_), 256, SMEM_MMA>>>(Vh, Vl, NV_, sV, RvTh, RvTl, sHC, MvT, nullptr, nullptr, sNC, H_);
    // 6. PqT = Vt^T·T2   [H,CO]  K=NV
    gemm_mma<2><<<dim3(4, H_/128, B_), 256, SMEM_MMA>>>(Vth, Vtl, H_, sV, T2h, T2l, sNC, nullptr, PqTh, PqTl, sHC, NV_);
    // 7. RqT = Wbt^T·PqT [H,CO]  K=H
    gemm_mma<2><<<dim3(4, H_/128, B_), 256, SMEM_MMA>>>(Wbth, Wbtl, H_, 0, PqTh, PqTl, sHC, nullptr, RqTh, RqTl, sHC, H_);
    // 8. MqT = Qt^T·RqT  [NQ,CO] K=H   (fp32 only)
    gemm_mma<1><<<dim3(4, NQ_/128, B_), 256, SMEM_MMA>>>(Qth, Qtl, NQ_, sQ, RqTh, RqTl, sHC, MqT, nullptr, nullptr, sNC, H_);

    logits_t<<<dim3(NV_/8, B_), 256>>>(T2, MvT, w_hv, logv, NV_);
    logits_t<<<dim3(NQ_/8, B_), 256>>>(T1, MqT, w_hq, logq, NQ_);

    float* out_av = out;
    float* out_aq = out + (size_t)B_ * NV_;
    float* out_v  = out + (size_t)B_ * (NV_ + NQ_);
    float* out_q  = out_v + (size_t)B_ * H_;

    softmax_kernel<<<B_, 256>>>(logv, out_av, NV_);
    softmax_kernel<<<B_, 256>>>(logq, out_aq, NQ_);

    wdot_kernel<<<dim3(H_/8, B_), 256>>>(out_av, V, out_v, NV_);
    aq_Q_partial<<<dim3(16, B_), 1024>>>(out_aq, Q, part);
    aq_Q_reduce<<<B_, 1024>>>(part, out_q);
}

// round 10
// speedup vs baseline: 1.7793x; 1.7793x over previous
#include <cuda_runtime.h>
#include <cuda_fp16.h>
#include <math.h>
#include <stdint.h>

constexpr int B_  = 16;
constexpr int H_  = 1024;
constexpr int CO_ = 512;
constexpr int NV_ = 2048;
constexpr int NQ_ = 2048;

// packed (uint32 = 2 fp16) operand sizes, per-batch counts
constexpr size_t PQ  = (size_t)(NQ_/2) * H_;    // Qp  [NQ/2][H]
constexpr size_t PQT = (size_t)(H_/2) * NQ_;    // Qtp [H/2][NQ]
constexpr size_t PV  = (size_t)(H_/2) * NV_;    // Vp  [H/2][NV]
constexpr size_t PVT = (size_t)(NV_/2) * H_;    // Vtp [NV/2][H]
constexpr size_t PW  = (size_t)(H_/2) * H_;
constexpr size_t PWC = (size_t)(H_/2) * CO_;
constexpr size_t PNC = (size_t)(NQ_/2) * CO_;   // T1p/T2p
constexpr size_t PHC = (size_t)(H_/2) * CO_;    // PvTp/RvTp

__device__ uint32_t g_Qp  [PQ  * B_], g_Qph [PQ  * B_];
__device__ uint32_t g_Qtp [PQT * B_], g_Qtph[PQT * B_];
__device__ uint32_t g_Vp  [PV  * B_], g_Vph [PV  * B_];
__device__ uint32_t g_Vtp [PVT * B_], g_Vtph[PVT * B_];
__device__ uint32_t g_Wbp [PW], g_Wbph[PW], g_Wbtp[PW], g_Wbtph[PW];
__device__ uint32_t g_WqTp[PWC], g_WqTph[PWC], g_WvTp[PWC], g_WvTph[PWC];
__device__ uint32_t g_T1p [PNC * B_], g_T1ph[PNC * B_];
__device__ uint32_t g_T2p [PNC * B_], g_T2ph[PNC * B_];
__device__ uint32_t g_PvTp[PHC * B_], g_PvTph[PHC * B_];   // also PqTp
__device__ uint32_t g_RvTp[PHC * B_], g_RvTph[PHC * B_];   // also RqTp

__device__ float g_T1 [(size_t)B_ * NQ_ * CO_];
__device__ float g_T2 [(size_t)B_ * NV_ * CO_];
__device__ float g_PvT[(size_t)B_ * H_ * CO_];   // also PqT
__device__ float g_RvT[(size_t)B_ * H_ * CO_];   // also RqT
__device__ float g_MvT[(size_t)B_ * NV_ * CO_];
__device__ float g_MqT[(size_t)B_ * NQ_ * CO_];
__device__ float g_logv[(size_t)B_ * NV_], g_logq[(size_t)B_ * NQ_];
__device__ float g_part[(size_t)B_ * 16 * H_];

__device__ __forceinline__ uint32_t smem_u32(const void* p) {
    uint32_t a;
    asm("{ .reg .u64 t; cvta.to.shared.u64 t, %1; cvt.u32.u64 %0, t; }" : "=r"(a) : "l"(p));
    return a;
}
#define CPA16(dst, src) \
    asm volatile("cp.async.cg.shared.global [%0], [%1], 16;" :: "r"(dst), "l"(src))
#define CP_COMMIT() asm volatile("cp.async.commit_group;" ::: "memory")
#define CP_WAIT1()  asm volatile("cp.async.wait_group 1;" ::: "memory")

// split x0,x1 (already scaled) into packed h0-pair and h1-pair
__device__ __forceinline__ void pack2(float x0, float x1, uint32_t& u0, uint32_t& u1) {
    __half a0 = __float2half_rn(x0), a1 = __float2half_rn(x1);
    float r0 = x0 - __half2float(a0), r1 = x1 - __half2float(a1);
    __half b0 = __float2half_rn(r0), b1 = __float2half_rn(r1);
    u0 = (uint32_t)__half_as_ushort(a0) | ((uint32_t)__half_as_ushort(a1) << 16);
    u1 = (uint32_t)__half_as_ushort(b0) | ((uint32_t)__half_as_ushort(b1) << 16);
}
__device__ __forceinline__ void mma16(float* c, const uint32_t* a, const uint32_t* b) {
    asm volatile(
        "mma.sync.aligned.m16n8k16.row.col.f32.f16.f16.f32 "
        "{%0,%1,%2,%3}, {%4,%5,%6,%7}, {%8,%9}, {%0,%1,%2,%3};"
        : "+f"(c[0]), "+f"(c[1]), "+f"(c[2]), "+f"(c[3])
        : "r"(a[0]), "r"(a[1]), "r"(a[2]), "r"(a[3]), "r"(b[0]), "r"(b[1]));
}

// ---------------------------------------------------------------------------
// C[M,512] = A^T*B, fp16x2 emulation, pre-packed operands.
// Ah/Al: [K/2][M-global] u32 (row stride lda), Bh/Bl: [K/2][512] u32.
// Block 128x128, 8 warps 64x32, K-slab 32 (16 kpair rows), 3-stage cp.async.
// grid = (4, M/128, batch). Epilogue: fp32 C = acc * outScale.
// ---------------------------------------------------------------------------
constexpr int SROW = 136;                  // u32 per smem row
constexpr int TILE_U = 16 * SROW;
constexpr int STG_U = 4 * TILE_U;          // Ah,Al,Bh,Bl
constexpr int SMEM_MMA = 3 * STG_U * 4;    // 104448 B

__global__ __launch_bounds__(256, 2)
void gemm_fp16x2(const uint32_t* __restrict__ Ah, const uint32_t* __restrict__ Al,
                 int lda, size_t sA,
                 const uint32_t* __restrict__ Bh, const uint32_t* __restrict__ Bl,
                 size_t sB, float* __restrict__ C, size_t sC, int K, float outScale)
{
    extern __shared__ __align__(16) uint32_t sm[];
    const int tid = threadIdx.x;
    const int bx = blockIdx.x, by = blockIdx.y, bz = blockIdx.z;

    const uint32_t* gAh = Ah + (size_t)bz * sA + by * 128;
    const uint32_t* gAl = Al + (size_t)bz * sA + by * 128;
    const uint32_t* gBh = Bh + (size_t)bz * sB + bx * 128;
    const uint32_t* gBl = Bl + (size_t)bz * sB + bx * 128;

    const int lane = tid & 31, w = tid >> 5;
    const int g = lane >> 2, t = lane & 3;
    const int rbase = (w & 1) * 64;
    const int cbase = (w >> 1) * 32;

    const uint32_t smb = smem_u32(sm);
    const int srow = tid >> 4;          // kpair row 0..15
    const int scol = (tid & 15) * 8;    // 8 u32 = 2 x 16B

    float c[4][4][4];
#pragma unroll
    for (int i = 0; i < 4; ++i)
#pragma unroll
        for (int j = 0; j < 4; ++j)
#pragma unroll
            for (int k = 0; k < 4; ++k) c[i][j][k] = 0.f;

    const int T = K >> 5;
    const uint32_t doff = (uint32_t)(srow * SROW + scol) * 4;

#define STAGE_LOADS(sidx, kp0) do {                                             \
    const uint32_t base_ = smb + (uint32_t)(sidx) * (STG_U * 4);                \
    const size_t kr_ = (size_t)((kp0) + srow);                                  \
    CPA16(base_ + doff,                    gAh + kr_ * lda + scol);             \
    CPA16(base_ + doff + 16,               gAh + kr_ * lda + scol + 4);         \
    CPA16(base_ + TILE_U*4 + doff,         gAl + kr_ * lda + scol);             \
    CPA16(base_ + TILE_U*4 + doff + 16,    gAl + kr_ * lda + scol + 4);         \
    CPA16(base_ + 2*TILE_U*4 + doff,       gBh + kr_ * 512 + scol);             \
    CPA16(base_ + 2*TILE_U*4 + doff + 16,  gBh + kr_ * 512 + scol + 4);         \
    CPA16(base_ + 3*TILE_U*4 + doff,       gBl + kr_ * 512 + scol);             \
    CPA16(base_ + 3*TILE_U*4 + doff + 16,  gBl + kr_ * 512 + scol + 4);         \
} while (0)

#pragma unroll
    for (int s = 0; s < 3; ++s) {
        STAGE_LOADS(s, s * 16);
        CP_COMMIT();
    }

    int buf = 0;
    for (int tt = 0; tt < T; ++tt) {
        CP_WAIT1();
        __syncthreads();

        const uint32_t* Ahs = sm + buf * STG_U;
        const uint32_t* Als = Ahs + TILE_U;
        const uint32_t* Bhs = Als + TILE_U;
        const uint32_t* Bls = Bhs + TILE_U;
#pragma unroll
        for (int ks = 0; ks < 2; ++ks) {
            const int kr = ks * 8 + t;
            const uint32_t* aph = Ahs + kr * SROW;
            const uint32_t* apl = Als + kr * SROW;
            const uint32_t* bph = Bhs + kr * SROW;
            const uint32_t* bpl = Bls + kr * SROW;
            uint32_t ah[4][4], al[4][4], bh[4][2], bl[4][2];
#pragma unroll
            for (int i = 0; i < 4; ++i) {
                const int m = rbase + i * 16 + g;
                ah[i][0] = aph[m];            al[i][0] = apl[m];
                ah[i][1] = aph[m + 8];        al[i][1] = apl[m + 8];
                ah[i][2] = aph[4*SROW + m];   al[i][2] = apl[4*SROW + m];
                ah[i][3] = aph[4*SROW + m+8]; al[i][3] = apl[4*SROW + m+8];
            }
#pragma unroll
            for (int j = 0; j < 4; ++j) {
                const int n = cbase + j * 8 + g;
                bh[j][0] = bph[n];            bl[j][0] = bpl[n];
                bh[j][1] = bph[4*SROW + n];   bl[j][1] = bpl[4*SROW + n];
            }
#pragma unroll
            for (int i = 0; i < 4; ++i)
#pragma unroll
                for (int j = 0; j < 4; ++j) {
                    mma16(c[i][j], ah[i], bl[j]);
                    mma16(c[i][j], al[i], bh[j]);
                    mma16(c[i][j], ah[i], bh[j]);
                }
        }
        __syncthreads();

        if (tt + 3 < T) STAGE_LOADS(buf, (tt + 3) * 16);
        CP_COMMIT();
        buf = (buf == 2) ? 0 : buf + 1;
    }
#undef STAGE_LOADS

    const size_t coff = (size_t)bz * sC + (size_t)(by * 128) * 512 + bx * 128;
#pragma unroll
    for (int i = 0; i < 4; ++i) {
        const int r0 = rbase + i * 16 + g;
#pragma unroll
        for (int j = 0; j < 4; ++j) {
            const int cc = cbase + j * 8 + 2 * t;
            *reinterpret_cast<float2*>(C + coff + (size_t)r0 * 512 + cc) =
                make_float2(c[i][j][0] * outScale, c[i][j][1] * outScale);
            *reinterpret_cast<float2*>(C + coff + (size_t)(r0 + 8) * 512 + cc) =
                make_float2(c[i][j][2] * outScale, c[i][j][3] * outScale);
        }
    }
}

// ------ straight pack: src[K][M] f32 -> h0,h1 [K/2][M] u32, scaled -------
// grid (M/256, K/2, batch)
__global__ void pack_k(const float* __restrict__ src, uint32_t* __restrict__ h0,
                       uint32_t* __restrict__ h1, int M, float s, size_t sS, size_t sD)
{
    const int m = blockIdx.x * 256 + threadIdx.x;
    const int kp = blockIdx.y;
    const float* sp = src + (size_t)blockIdx.z * sS + (size_t)(2 * kp) * M + m;
    uint32_t u0, u1;
    pack2(sp[0] * s, sp[M] * s, u0, u1);
    const size_t o = (size_t)blockIdx.z * sD + (size_t)kp * M + m;
    h0[o] = u0; h1[o] = u1;
}

// --- transpose pack: src[R][C] f32 -> h0,h1 [C/2][R] u32 (pairs along C) ---
// grid (C/32, R/32, batch), block (32, 8)
__global__ void tpack_k(const float* __restrict__ src, uint32_t* __restrict__ h0,
                        uint32_t* __restrict__ h1, int R, int C, float s,
                        size_t sS, size_t sD)
{
    __shared__ float tile[32][33];
    const size_t so = (size_t)blockIdx.z * sS;
    const int x0 = blockIdx.x * 32, y0 = blockIdx.y * 32;
    for (int j = threadIdx.y; j < 32; j += 8)
        tile[j][threadIdx.x] = src[so + (size_t)(y0 + j) * C + x0 + threadIdx.x];
    __syncthreads();
    const int tx = threadIdx.x;
    for (int kpl = threadIdx.y; kpl < 16; kpl += 8) {
        uint32_t u0, u1;
        pack2(tile[tx][2 * kpl] * s, tile[tx][2 * kpl + 1] * s, u0, u1);
        const size_t o = (size_t)blockIdx.z * sD + (size_t)(x0 / 2 + kpl) * R + y0 + tx;
        h0[o] = u0; h1[o] = u1;
    }
}

// -------- logits[b,n] = sum_c w[c]*tanh(X[b,n,c]+Y[b,n,c]); warp per n -----
__global__ void logits_t(const float* __restrict__ X, const float* __restrict__ Y,
                         const float* __restrict__ w, float* __restrict__ lg, int Ncol)
{
    const int b = blockIdx.y;
    const int n = blockIdx.x * 8 + (threadIdx.x >> 5);
    const int lane = threadIdx.x & 31;
    const float* xp = X + ((size_t)b * Ncol + n) * CO_;
    const float* yp = Y + ((size_t)b * Ncol + n) * CO_;
    float acc = 0.f;
#pragma unroll 4
    for (int c = lane; c < CO_; c += 32)
        acc += w[c] * tanhf(xp[c] + yp[c]);
#pragma unroll
    for (int off = 16; off > 0; off >>= 1)
        acc += __shfl_down_sync(0xffffffffu, acc, off);
    if (lane == 0) lg[(size_t)b * Ncol + n] = acc;
}

__global__ void softmax_kernel(const float* __restrict__ lg, float* __restrict__ outp, int Ncol)
{
    __shared__ float buf[2048];
    __shared__ float red[256];
    const int b = blockIdx.x, tid = threadIdx.x;
    const float* x = lg + (size_t)b * Ncol;
    float mx = -INFINITY;
    for (int i = tid; i < Ncol; i += 256) { float v = x[i]; buf[i] = v; mx = fmaxf(mx, v); }
    red[tid] = mx; __syncthreads();
    for (int s = 128; s > 0; s >>= 1) { if (tid < s) red[tid] = fmaxf(red[tid], red[tid + s]); __syncthreads(); }
    mx = red[0]; __syncthreads();
    float sm = 0.f;
    for (int i = tid; i < Ncol; i += 256) { float e = expf(buf[i] - mx); buf[i] = e; sm += e; }
    red[tid] = sm; __syncthreads();
    for (int s = 128; s > 0; s >>= 1) { if (tid < s) red[tid] += red[tid + s]; __syncthreads(); }
    const float inv = 1.f / red[0];
    for (int i = tid; i < Ncol; i += 256) outp[(size_t)b * Ncol + i] = buf[i] * inv;
}

__global__ void wdot_kernel(const float* __restrict__ a, const float* __restrict__ X,
                            float* __restrict__ outv, int Ncol)
{
    const int b = blockIdx.y;
    const int h = blockIdx.x * 8 + (threadIdx.x >> 5);
    const int lane = threadIdx.x & 31;
    const float* row = X + ((size_t)b * H_ + h) * Ncol;
    const float* av = a + (size_t)b * Ncol;
    float acc = 0.f;
    for (int i = lane; i < Ncol; i += 32) acc += av[i] * row[i];
#pragma unroll
    for (int off = 16; off > 0; off >>= 1) acc += __shfl_down_sync(0xffffffffu, acc, off);
    if (lane == 0) outv[(size_t)b * H_ + h] = acc;
}

__global__ void aq_Q_partial(const float* __restrict__ a, const float* __restrict__ Q,
                             float* __restrict__ part)
{
    const int b = blockIdx.y, j = blockIdx.x;
    const int h = threadIdx.x;
    const float* aq = a + (size_t)b * NQ_;
    float acc = 0.f;
    const int q0 = j * (NQ_ / 16);
    for (int q = q0; q < q0 + NQ_ / 16; ++q)
        acc += aq[q] * Q[((size_t)b * NQ_ + q) * H_ + h];
    part[((size_t)b * 16 + j) * H_ + h] = acc;
}
__global__ void aq_Q_reduce(const float* __restrict__ part, float* __restrict__ outq)
{
    const int b = blockIdx.x;
    const int h = threadIdx.x;
    float acc = 0.f;
#pragma unroll
    for (int j = 0; j < 16; ++j)
        acc += part[((size_t)b * 16 + j) * H_ + h];
    outq[(size_t)b * H_ + h] = acc;
}

// ---------------------------------------------------------------------------
extern "C" void kernel_launch(void* const* d_in, const int* in_sizes, int n_in,
                              void* d_out, int out_size)
{
    const float* V    = (const float*)d_in[0];  // [B, H, NV]
    const float* Q    = (const float*)d_in[1];  // [B, NQ, H]
    const float* W_b  = (const float*)d_in[2];  // [H, H]
    const float* W_v  = (const float*)d_in[3];  // [CO, H]
    const float* W_q  = (const float*)d_in[4];  // [CO, H]
    const float* w_hv = (const float*)d_in[5];
    const float* w_hq = (const float*)d_in[6];
    float* out = (float*)d_out;

#define USYM(p, s) uint32_t* p; cudaGetSymbolAddress((void**)&p, s)
#define FSYM(p, s) float* p;    cudaGetSymbolAddress((void**)&p, s)
    USYM(Qp, g_Qp);     USYM(Qph, g_Qph);
    USYM(Qtp, g_Qtp);   USYM(Qtph, g_Qtph);
    USYM(Vp, g_Vp);     USYM(Vph, g_Vph);
    USYM(Vtp, g_Vtp);   USYM(Vtph, g_Vtph);
    USYM(Wbp, g_Wbp);   USYM(Wbph, g_Wbph);
    USYM(Wbtp, g_Wbtp); USYM(Wbtph, g_Wbtph);
    USYM(WqTp, g_WqTp); USYM(WqTph, g_WqTph);
    USYM(WvTp, g_WvTp); USYM(WvTph, g_WvTph);
    USYM(T1p, g_T1p);   USYM(T1ph, g_T1ph);
    USYM(T2p, g_T2p);   USYM(T2ph, g_T2ph);
    USYM(PvTp, g_PvTp); USYM(PvTph, g_PvTph);
    USYM(RvTp, g_RvTp); USYM(RvTph, g_RvTph);
    FSYM(T1, g_T1);   FSYM(T2, g_T2);
    FSYM(PvT, g_PvT); FSYM(RvT, g_RvT);
    FSYM(MvT, g_MvT); FSYM(MqT, g_MqT);
    FSYM(logv, g_logv); FSYM(logq, g_logq); FSYM(part, g_part);
#undef USYM
#undef FSYM

    cudaFuncSetAttribute(gemm_fp16x2, cudaFuncAttributeMaxDynamicSharedMemorySize, SMEM_MMA);

    const size_t sQ = (size_t)NQ_ * H_, sV = (size_t)H_ * NV_;
    const size_t sNC = (size_t)NQ_ * CO_, sHC = (size_t)H_ * CO_;
    const float S = 0.0625f;   // 1/16 intermediate pack scale
    const float R16 = 16.0f;

    // pre-pass packs (inputs, scale 1)
    pack_k <<<dim3(H_/256, NQ_/2, B_), 256>>>(Q, Qp, Qph, H_, 1.f, sQ, PQ);
    pack_k <<<dim3(NV_/256, H_/2, B_), 256>>>(V, Vp, Vph, NV_, 1.f, sV, PV);
    pack_k <<<dim3(H_/256, H_/2, 1),  256>>>(W_b, Wbp, Wbph, H_, 1.f, 0, 0);
    tpack_k<<<dim3(H_/32, NQ_/32, B_), dim3(32, 8)>>>(Q, Qtp, Qtph, NQ_, H_, 1.f, sQ, PQT);
    tpack_k<<<dim3(NV_/32, H_/32, B_), dim3(32, 8)>>>(V, Vtp, Vtph, H_, NV_, 1.f, sV, PVT);
    tpack_k<<<dim3(H_/32, H_/32, 1),  dim3(32, 8)>>>(W_b, Wbtp, Wbtph, H_, H_, 1.f, 0, 0);
    tpack_k<<<dim3(H_/32, CO_/32, 1), dim3(32, 8)>>>(W_q, WqTp, WqTph, CO_, H_, 1.f, 0, 0);
    tpack_k<<<dim3(H_/32, CO_/32, 1), dim3(32, 8)>>>(W_v, WvTp, WvTph, CO_, H_, 1.f, 0, 0);

    // G1: T1 = Qt^T·WqT  [NQ,512] K=H
    gemm_fp16x2<<<dim3(4, NQ_/128, B_), 256, SMEM_MMA>>>(Qtp, Qtph, NQ_, PQT, WqTp, WqTph, 0, T1, sNC, H_, 1.f);
    pack_k<<<dim3(CO_/256, NQ_/2, B_), 256>>>(T1, T1p, T1ph, CO_, S, sNC, PNC);
    // G2: T2 = V^T·WvT   [NV,512] K=H
    gemm_fp16x2<<<dim3(4, NV_/128, B_), 256, SMEM_MMA>>>(Vp, Vph, NV_, PV, WvTp, WvTph, 0, T2, sNC, H_, 1.f);
    pack_k<<<dim3(CO_/256, NV_/2, B_), 256>>>(T2, T2p, T2ph, CO_, S, sNC, PNC);
    // G3: PvT = Q^T·T1   [H,512] K=NQ
    gemm_fp16x2<<<dim3(4, H_/128, B_), 256, SMEM_MMA>>>(Qp, Qph, H_, PQ, T1p, T1ph, PNC, PvT, sHC, NQ_, R16);
    pack_k<<<dim3(CO_/256, H_/2, B_), 256>>>(PvT, PvTp, PvTph, CO_, S, sHC, PHC);
    // G4: RvT = Wb^T·PvT [H,512] K=H
    gemm_fp16x2<<<dim3(4, H_/128, B_), 256, SMEM_MMA>>>(Wbp, Wbph, H_, 0, PvTp, PvTph, PHC, RvT, sHC, H_, R16);
    pack_k<<<dim3(CO_/256, H_/2, B_), 256>>>(RvT, RvTp, RvTph, CO_, S, sHC, PHC);
    // G5: MvT = V^T·RvT  [NV,512] K=H
    gemm_fp16x2<<<dim3(4, NV_/128, B_), 256, SMEM_MMA>>>(Vp, Vph, NV_, PV, RvTp, RvTph, PHC, MvT, sNC, H_, R16);
    // G6: PqT = Vt^T·T2  [H,512] K=NV   (reuse PvT buffers)
    gemm_fp16x2<<<dim3(4, H_/128, B_), 256, SMEM_MMA>>>(Vtp, Vtph, H_, PVT, T2p, T2ph, PNC, PvT, sHC, NV_, R16);
    pack_k<<<dim3(CO_/256, H_/2, B_), 256>>>(PvT, PvTp, PvTph, CO_, S, sHC, PHC);
    // G7: RqT = Wbt^T·PqT [H,512] K=H  (reuse RvT buffers)
    gemm_fp16x2<<<dim3(4, H_/128, B_), 256, SMEM_MMA>>>(Wbtp, Wbtph, H_, 0, PvTp, PvTph, PHC, RvT, sHC, H_, R16);
    pack_k<<<dim3(CO_/256, H_/2, B_), 256>>>(RvT, RvTp, RvTph, CO_, S, sHC, PHC);
    // G8: MqT = Qt^T·RqT [NQ,512] K=H
    gemm_fp16x2<<<dim3(4, NQ_/128, B_), 256, SMEM_MMA>>>(Qtp, Qtph, NQ_, PQT, RvTp, RvTph, PHC, MqT, sNC, H_, R16);

    logits_t<<<dim3(NV_/8, B_), 256>>>(T2, MvT, w_hv, logv, NV_);
    logits_t<<<dim3(NQ_/8, B_), 256>>>(T1, MqT, w_hq, logq, NQ_);

    float* out_av = out;
    float* out_aq = out + (size_t)B_ * NV_;
    float* out_v  = out + (size_t)B_ * (NV_ + NQ_);
    float* out_q  = out_v + (size_t)B_ * H_;

    softmax_kernel<<<B_, 256>>>(logv, out_av, NV_);
    softmax_kernel<<<B_, 256>>>(logq, out_aq, NQ_);

    wdot_kernel<<<dim3(H_/8, B_), 256>>>(out_av, V, out_v, NV_);
    aq_Q_partial<<<dim3(16, B_), 1024>>>(out_aq, Q, part);
    aq_Q_reduce<<<B_, 1024>>>(part, out_q);
}

// round 11
// speedup vs baseline: 1.9004x; 1.0681x over previous
#include <cuda_runtime.h>
#include <cuda_fp16.h>
#include <math.h>
#include <stdint.h>

constexpr int B_  = 16;
constexpr int H_  = 1024;
constexpr int CO_ = 512;
constexpr int NV_ = 2048;
constexpr int NQ_ = 2048;

// packed (uint32 = 2 fp16) operand sizes, per-batch counts
constexpr size_t PQ  = (size_t)(NQ_/2) * H_;    // Qp  [NQ/2][H]
constexpr size_t PQT = (size_t)(H_/2) * NQ_;    // Qtp [H/2][NQ]
constexpr size_t PV  = (size_t)(H_/2) * NV_;    // Vp  [H/2][NV]
constexpr size_t PVT = (size_t)(NV_/2) * H_;    // Vtp [NV/2][H]
constexpr size_t PW  = (size_t)(H_/2) * H_;
constexpr size_t PWC = (size_t)(H_/2) * CO_;
constexpr size_t PNC = (size_t)(NQ_/2) * CO_;   // T1p/T2p
constexpr size_t PHC = (size_t)(H_/2) * CO_;    // PvTp/RvTp

__device__ uint32_t g_Qp  [PQ  * B_], g_Qph [PQ  * B_];
__device__ uint32_t g_Qtp [PQT * B_], g_Qtph[PQT * B_];
__device__ uint32_t g_Vp  [PV  * B_], g_Vph [PV  * B_];
__device__ uint32_t g_Vtp [PVT * B_], g_Vtph[PVT * B_];
__device__ uint32_t g_Wbp [PW], g_Wbph[PW], g_Wbtp[PW], g_Wbtph[PW];
__device__ uint32_t g_WqTp[PWC], g_WqTph[PWC], g_WvTp[PWC], g_WvTph[PWC];
__device__ uint32_t g_T1p [PNC * B_], g_T1ph[PNC * B_];
__device__ uint32_t g_T2p [PNC * B_], g_T2ph[PNC * B_];
__device__ uint32_t g_PvTp[PHC * B_], g_PvTph[PHC * B_];   // also PqTp
__device__ uint32_t g_RvTp[PHC * B_], g_RvTph[PHC * B_];   // also RqTp

__device__ float g_T1 [(size_t)B_ * NQ_ * CO_];
__device__ float g_T2 [(size_t)B_ * NV_ * CO_];
__device__ float g_MvT[(size_t)B_ * NV_ * CO_];
__device__ float g_MqT[(size_t)B_ * NQ_ * CO_];
__device__ float g_logv[(size_t)B_ * NV_], g_logq[(size_t)B_ * NQ_];
__device__ float g_part[(size_t)B_ * 16 * H_];

__device__ __forceinline__ uint32_t smem_u32(const void* p) {
    uint32_t a;
    asm("{ .reg .u64 t; cvta.to.shared.u64 t, %1; cvt.u32.u64 %0, t; }" : "=r"(a) : "l"(p));
    return a;
}
#define CPA16(dst, src) \
    asm volatile("cp.async.cg.shared.global [%0], [%1], 16;" :: "r"(dst), "l"(src))
#define CP_COMMIT() asm volatile("cp.async.commit_group;" ::: "memory")
#define CP_WAIT1()  asm volatile("cp.async.wait_group 1;" ::: "memory")

// split x0,x1 (already scaled) into packed h0-pair and h1-pair
__device__ __forceinline__ void pack2(float x0, float x1, uint32_t& u0, uint32_t& u1) {
    __half a0 = __float2half_rn(x0), a1 = __float2half_rn(x1);
    float r0 = x0 - __half2float(a0), r1 = x1 - __half2float(a1);
    __half b0 = __float2half_rn(r0), b1 = __float2half_rn(r1);
    u0 = (uint32_t)__half_as_ushort(a0) | ((uint32_t)__half_as_ushort(a1) << 16);
    u1 = (uint32_t)__half_as_ushort(b0) | ((uint32_t)__half_as_ushort(b1) << 16);
}
__device__ __forceinline__ void mma16(float* c, const uint32_t* a, const uint32_t* b) {
    asm volatile(
        "mma.sync.aligned.m16n8k16.row.col.f32.f16.f16.f32 "
        "{%0,%1,%2,%3}, {%4,%5,%6,%7}, {%8,%9}, {%0,%1,%2,%3};"
        : "+f"(c[0]), "+f"(c[1]), "+f"(c[2]), "+f"(c[3])
        : "r"(a[0]), "r"(a[1]), "r"(a[2]), "r"(a[3]), "r"(b[0]), "r"(b[1]));
}

// ---------------------------------------------------------------------------
// C[M,512] = A^T*B, fp16x2 emulation, pre-packed operands.
// Ah/Al: [K/2][M-global] u32 (row stride lda), Bh/Bl: [K/2][512] u32.
// Block 128x128, 8 warps 64x32, K-slab 32 (16 kpair rows), 3-stage cp.async.
// grid = (4, M/128, batch).
// EPI bit0: write fp32 C (C = acc*outScale).
// EPI bit1: write packed hi/lo (value = acc*packScale) via smem repack.
// ---------------------------------------------------------------------------
constexpr int SROW = 136;                  // u32 per smem row
constexpr int TILE_U = 16 * SROW;
constexpr int STG_U = 4 * TILE_U;          // Ah,Al,Bh,Bl
constexpr int SMEM_MMA = 3 * STG_U * 4;    // 104448 B (>= 128*132*4 epi tile)

template <int EPI>
__global__ __launch_bounds__(256, 2)
void gemm_fp16x2(const uint32_t* __restrict__ Ah, const uint32_t* __restrict__ Al,
                 int lda, size_t sA,
                 const uint32_t* __restrict__ Bh, const uint32_t* __restrict__ Bl,
                 size_t sB, float* __restrict__ C, size_t sC,
                 uint32_t* __restrict__ Ph, uint32_t* __restrict__ Pl, size_t sP,
                 int K, float outScale, float packScale)
{
    extern __shared__ __align__(16) uint32_t sm[];
    const int tid = threadIdx.x;
    const int bx = blockIdx.x, by = blockIdx.y, bz = blockIdx.z;

    const uint32_t* gAh = Ah + (size_t)bz * sA + by * 128;
    const uint32_t* gAl = Al + (size_t)bz * sA + by * 128;
    const uint32_t* gBh = Bh + (size_t)bz * sB + bx * 128;
    const uint32_t* gBl = Bl + (size_t)bz * sB + bx * 128;

    const int lane = tid & 31, w = tid >> 5;
    const int g = lane >> 2, t = lane & 3;
    const int rbase = (w & 1) * 64;
    const int cbase = (w >> 1) * 32;

    const uint32_t smb = smem_u32(sm);
    const int srow = tid >> 4;          // kpair row 0..15
    const int scol = (tid & 15) * 8;    // 8 u32 = 2 x 16B

    float c[4][4][4];
#pragma unroll
    for (int i = 0; i < 4; ++i)
#pragma unroll
        for (int j = 0; j < 4; ++j)
#pragma unroll
            for (int k = 0; k < 4; ++k) c[i][j][k] = 0.f;

    const int T = K >> 5;
    const uint32_t doff = (uint32_t)(srow * SROW + scol) * 4;

#define STAGE_LOADS(sidx, kp0) do {                                             \
    const uint32_t base_ = smb + (uint32_t)(sidx) * (STG_U * 4);                \
    const size_t kr_ = (size_t)((kp0) + srow);                                  \
    CPA16(base_ + doff,                    gAh + kr_ * lda + scol);             \
    CPA16(base_ + doff + 16,               gAh + kr_ * lda + scol + 4);         \
    CPA16(base_ + TILE_U*4 + doff,         gAl + kr_ * lda + scol);             \
    CPA16(base_ + TILE_U*4 + doff + 16,    gAl + kr_ * lda + scol + 4);         \
    CPA16(base_ + 2*TILE_U*4 + doff,       gBh + kr_ * 512 + scol);             \
    CPA16(base_ + 2*TILE_U*4 + doff + 16,  gBh + kr_ * 512 + scol + 4);         \
    CPA16(base_ + 3*TILE_U*4 + doff,       gBl + kr_ * 512 + scol);             \
    CPA16(base_ + 3*TILE_U*4 + doff + 16,  gBl + kr_ * 512 + scol + 4);         \
} while (0)

#pragma unroll
    for (int s = 0; s < 3; ++s) {
        STAGE_LOADS(s, s * 16);
        CP_COMMIT();
    }

    int buf = 0;
    for (int tt = 0; tt < T; ++tt) {
        CP_WAIT1();
        __syncthreads();

        const uint32_t* Ahs = sm + buf * STG_U;
        const uint32_t* Als = Ahs + TILE_U;
        const uint32_t* Bhs = Als + TILE_U;
        const uint32_t* Bls = Bhs + TILE_U;
#pragma unroll
        for (int ks = 0; ks < 2; ++ks) {
            const int kr = ks * 8 + t;
            const uint32_t* aph = Ahs + kr * SROW;
            const uint32_t* apl = Als + kr * SROW;
            const uint32_t* bph = Bhs + kr * SROW;
            const uint32_t* bpl = Bls + kr * SROW;
            uint32_t ah[4][4], al[4][4], bh[4][2], bl[4][2];
#pragma unroll
            for (int i = 0; i < 4; ++i) {
                const int m = rbase + i * 16 + g;
                ah[i][0] = aph[m];            al[i][0] = apl[m];
                ah[i][1] = aph[m + 8];        al[i][1] = apl[m + 8];
                ah[i][2] = aph[4*SROW + m];   al[i][2] = apl[4*SROW + m];
                ah[i][3] = aph[4*SROW + m+8]; al[i][3] = apl[4*SROW + m+8];
            }
#pragma unroll
            for (int j = 0; j < 4; ++j) {
                const int n = cbase + j * 8 + g;
                bh[j][0] = bph[n];            bl[j][0] = bpl[n];
                bh[j][1] = bph[4*SROW + n];   bl[j][1] = bpl[4*SROW + n];
            }
#pragma unroll
            for (int i = 0; i < 4; ++i)
#pragma unroll
                for (int j = 0; j < 4; ++j) {
                    mma16(c[i][j], ah[i], bl[j]);
                    mma16(c[i][j], al[i], bh[j]);
                    mma16(c[i][j], ah[i], bh[j]);
                }
        }
        __syncthreads();

        if (tt + 3 < T) STAGE_LOADS(buf, (tt + 3) * 16);
        CP_COMMIT();
        buf = (buf == 2) ? 0 : buf + 1;
    }
#undef STAGE_LOADS

    // ---------------- epilogue ----------------
    if (EPI & 1) {
        const size_t coff = (size_t)bz * sC + (size_t)(by * 128) * 512 + bx * 128;
#pragma unroll
        for (int i = 0; i < 4; ++i) {
            const int r0 = rbase + i * 16 + g;
#pragma unroll
            for (int j = 0; j < 4; ++j) {
                const int cc = cbase + j * 8 + 2 * t;
                *reinterpret_cast<float2*>(C + coff + (size_t)r0 * 512 + cc) =
                    make_float2(c[i][j][0] * outScale, c[i][j][1] * outScale);
                *reinterpret_cast<float2*>(C + coff + (size_t)(r0 + 8) * 512 + cc) =
                    make_float2(c[i][j][2] * outScale, c[i][j][3] * outScale);
            }
        }
    }
    if (EPI & 2) {
        // fp32 C tile -> smem (row stride 132), then pack adjacent-row pairs
        float* cs = reinterpret_cast<float*>(sm);   // mainloop done (last sync in loop)
#pragma unroll
        for (int i = 0; i < 4; ++i) {
            const int r0 = rbase + i * 16 + g;
#pragma unroll
            for (int j = 0; j < 4; ++j) {
                const int cc = cbase + j * 8 + 2 * t;
                *reinterpret_cast<float2*>(cs + r0 * 132 + cc) =
                    make_float2(c[i][j][0], c[i][j][1]);
                *reinterpret_cast<float2*>(cs + (r0 + 8) * 132 + cc) =
                    make_float2(c[i][j][2], c[i][j][3]);
            }
        }
        __syncthreads();
        const size_t poff = (size_t)bz * sP + (size_t)(by * 64) * 512 + bx * 128;
#pragma unroll 4
        for (int it = 0; it < 32; ++it) {
            const int idx = it * 256 + tid;       // 64 kpair rows x 128 cols
            const int kp = idx >> 7, cc2 = idx & 127;
            const float x0 = cs[(2 * kp) * 132 + cc2] * packScale;
            const float x1 = cs[(2 * kp + 1) * 132 + cc2] * packScale;
            uint32_t u0, u1;
            pack2(x0, x1, u0, u1);
            Ph[poff + (size_t)kp * 512 + cc2] = u0;
            Pl[poff + (size_t)kp * 512 + cc2] = u1;
        }
    }
}

// --- dual pack: src[R][C] -> straight [R/2][C] (pairs along R) AND
//                transposed [C/2][R] (pairs along C). grid (C/32, R/32, batch)
__global__ void dual_pack_k(const float* __restrict__ src,
                            uint32_t* __restrict__ sh0, uint32_t* __restrict__ sh1,
                            uint32_t* __restrict__ th0, uint32_t* __restrict__ th1,
                            int R, int C, size_t sS, size_t sSd, size_t sTd)
{
    __shared__ float tile[32][33];
    const size_t so = (size_t)blockIdx.z * sS;
    const int x0 = blockIdx.x * 32, y0 = blockIdx.y * 32;
    for (int j = threadIdx.y; j < 32; j += 8)
        tile[j][threadIdx.x] = src[so + (size_t)(y0 + j) * C + x0 + threadIdx.x];
    __syncthreads();
    const int tx = threadIdx.x;
    for (int kpl = threadIdx.y; kpl < 16; kpl += 8) {
        uint32_t u0, u1;
        pack2(tile[2 * kpl][tx], tile[2 * kpl + 1][tx], u0, u1);
        size_t o = (size_t)blockIdx.z * sSd + (size_t)(y0 / 2 + kpl) * C + x0 + tx;
        sh0[o] = u0; sh1[o] = u1;
        pack2(tile[tx][2 * kpl], tile[tx][2 * kpl + 1], u0, u1);
        o = (size_t)blockIdx.z * sTd + (size_t)(x0 / 2 + kpl) * R + y0 + tx;
        th0[o] = u0; th1[o] = u1;
    }
}

// --- transpose pack only: src[R][C] -> [C/2][R]. grid (C/32, R/32, batch) ---
__global__ void tpack_k(const float* __restrict__ src, uint32_t* __restrict__ h0,
                        uint32_t* __restrict__ h1, int R, int C, size_t sS, size_t sD)
{
    __shared__ float tile[32][33];
    const size_t so = (size_t)blockIdx.z * sS;
    const int x0 = blockIdx.x * 32, y0 = blockIdx.y * 32;
    for (int j = threadIdx.y; j < 32; j += 8)
        tile[j][threadIdx.x] = src[so + (size_t)(y0 + j) * C + x0 + threadIdx.x];
    __syncthreads();
    const int tx = threadIdx.x;
    for (int kpl = threadIdx.y; kpl < 16; kpl += 8) {
        uint32_t u0, u1;
        pack2(tile[tx][2 * kpl], tile[tx][2 * kpl + 1], u0, u1);
        const size_t o = (size_t)blockIdx.z * sD + (size_t)(x0 / 2 + kpl) * R + y0 + tx;
        h0[o] = u0; h1[o] = u1;
    }
}

// -------- logits[b,n] = sum_c w[c]*tanh(X[b,n,c]+Y[b,n,c]); warp per n -----
__global__ void logits_t(const float* __restrict__ X, const float* __restrict__ Y,
                         const float* __restrict__ w, float* __restrict__ lg, int Ncol)
{
    const int b = blockIdx.y;
    const int n = blockIdx.x * 8 + (threadIdx.x >> 5);
    const int lane = threadIdx.x & 31;
    const float* xp = X + ((size_t)b * Ncol + n) * CO_;
    const float* yp = Y + ((size_t)b * Ncol + n) * CO_;
    float acc = 0.f;
#pragma unroll 4
    for (int c = lane; c < CO_; c += 32)
        acc += w[c] * tanhf(xp[c] + yp[c]);
#pragma unroll
    for (int off = 16; off > 0; off >>= 1)
        acc += __shfl_down_sync(0xffffffffu, acc, off);
    if (lane == 0) lg[(size_t)b * Ncol + n] = acc;
}

__global__ void softmax_kernel(const float* __restrict__ lg, float* __restrict__ outp, int Ncol)
{
    __shared__ float buf[2048];
    __shared__ float red[256];
    const int b = blockIdx.x, tid = threadIdx.x;
    const float* x = lg + (size_t)b * Ncol;
    float mx = -INFINITY;
    for (int i = tid; i < Ncol; i += 256) { float v = x[i]; buf[i] = v; mx = fmaxf(mx, v); }
    red[tid] = mx; __syncthreads();
    for (int s = 128; s > 0; s >>= 1) { if (tid < s) red[tid] = fmaxf(red[tid], red[tid + s]); __syncthreads(); }
    mx = red[0]; __syncthreads();
    float sm = 0.f;
    for (int i = tid; i < Ncol; i += 256) { float e = expf(buf[i] - mx); buf[i] = e; sm += e; }
    red[tid] = sm; __syncthreads();
    for (int s = 128; s > 0; s >>= 1) { if (tid < s) red[tid] += red[tid + s]; __syncthreads(); }
    const float inv = 1.f / red[0];
    for (int i = tid; i < Ncol; i += 256) outp[(size_t)b * Ncol + i] = buf[i] * inv;
}

__global__ void wdot_kernel(const float* __restrict__ a, const float* __restrict__ X,
                            float* __restrict__ outv, int Ncol)
{
    const int b = blockIdx.y;
    const int h = blockIdx.x * 8 + (threadIdx.x >> 5);
    const int lane = threadIdx.x & 31;
    const float* row = X + ((size_t)b * H_ + h) * Ncol;
    const float* av = a + (size_t)b * Ncol;
    float acc = 0.f;
    for (int i = lane; i < Ncol; i += 32) acc += av[i] * row[i];
#pragma unroll
    for (int off = 16; off > 0; off >>= 1) acc += __shfl_down_sync(0xffffffffu, acc, off);
    if (lane == 0) outv[(size_t)b * H_ + h] = acc;
}

__global__ void aq_Q_partial(const float* __restrict__ a, const float* __restrict__ Q,
                             float* __restrict__ part)
{
    const int b = blockIdx.y, j = blockIdx.x;
    const int h = threadIdx.x;
    const float* aq = a + (size_t)b * NQ_;
    float acc = 0.f;
    const int q0 = j * (NQ_ / 16);
    for (int q = q0; q < q0 + NQ_ / 16; ++q)
        acc += aq[q] * Q[((size_t)b * NQ_ + q) * H_ + h];
    part[((size_t)b * 16 + j) * H_ + h] = acc;
}
__global__ void aq_Q_reduce(const float* __restrict__ part, float* __restrict__ outq)
{
    const int b = blockIdx.x;
    const int h = threadIdx.x;
    float acc = 0.f;
#pragma unroll
    for (int j = 0; j < 16; ++j)
        acc += part[((size_t)b * 16 + j) * H_ + h];
    outq[(size_t)b * H_ + h] = acc;
}

// ---------------------------------------------------------------------------
extern "C" void kernel_launch(void* const* d_in, const int* in_sizes, int n_in,
                              void* d_out, int out_size)
{
    const float* V    = (const float*)d_in[0];  // [B, H, NV]
    const float* Q    = (const float*)d_in[1];  // [B, NQ, H]
    const float* W_b  = (const float*)d_in[2];  // [H, H]
    const float* W_v  = (const float*)d_in[3];  // [CO, H]
    const float* W_q  = (const float*)d_in[4];  // [CO, H]
    const float* w_hv = (const float*)d_in[5];
    const float* w_hq = (const float*)d_in[6];
    float* out = (float*)d_out;

#define USYM(p, s) uint32_t* p; cudaGetSymbolAddress((void**)&p, s)
#define FSYM(p, s) float* p;    cudaGetSymbolAddress((void**)&p, s)
    USYM(Qp, g_Qp);     USYM(Qph, g_Qph);
    USYM(Qtp, g_Qtp);   USYM(Qtph, g_Qtph);
    USYM(Vp, g_Vp);     USYM(Vph, g_Vph);
    USYM(Vtp, g_Vtp);   USYM(Vtph, g_Vtph);
    USYM(Wbp, g_Wbp);   USYM(Wbph, g_Wbph);
    USYM(Wbtp, g_Wbtp); USYM(Wbtph, g_Wbtph);
    USYM(WqTp, g_WqTp); USYM(WqTph, g_WqTph);
    USYM(WvTp, g_WvTp); USYM(WvTph, g_WvTph);
    USYM(T1p, g_T1p);   USYM(T1ph, g_T1ph);
    USYM(T2p, g_T2p);   USYM(T2ph, g_T2ph);
    USYM(PvTp, g_PvTp); USYM(PvTph, g_PvTph);
    USYM(RvTp, g_RvTp); USYM(RvTph, g_RvTph);
    FSYM(T1, g_T1);   FSYM(T2, g_T2);
    FSYM(MvT, g_MvT); FSYM(MqT, g_MqT);
    FSYM(logv, g_logv); FSYM(logq, g_logq); FSYM(part, g_part);
#undef USYM
#undef FSYM

    cudaFuncSetAttribute(gemm_fp16x2<1>, cudaFuncAttributeMaxDynamicSharedMemorySize, SMEM_MMA);
    cudaFuncSetAttribute(gemm_fp16x2<2>, cudaFuncAttributeMaxDynamicSharedMemorySize, SMEM_MMA);
    cudaFuncSetAttribute(gemm_fp16x2<3>, cudaFuncAttributeMaxDynamicSharedMemorySize, SMEM_MMA);

    const size_t sQ = (size_t)NQ_ * H_, sV = (size_t)H_ * NV_;
    const size_t sNC = (size_t)NQ_ * CO_;
    const float S = 0.0625f;    // 1/16 intermediate pack scale
    const float R16 = 16.0f;

    // pre-pass: dual packs (one read of Q, V, W_b) + weight transpose packs
    dual_pack_k<<<dim3(H_/32, NQ_/32, B_), dim3(32, 8)>>>(Q, Qp, Qph, Qtp, Qtph, NQ_, H_, sQ, PQ, PQT);
    dual_pack_k<<<dim3(NV_/32, H_/32, B_), dim3(32, 8)>>>(V, Vp, Vph, Vtp, Vtph, H_, NV_, sV, PV, PVT);
    dual_pack_k<<<dim3(H_/32, H_/32, 1),  dim3(32, 8)>>>(W_b, Wbp, Wbph, Wbtp, Wbtph, H_, H_, 0, 0, 0);
    tpack_k<<<dim3(H_/32, CO_/32, 1), dim3(32, 8)>>>(W_q, WqTp, WqTph, CO_, H_, 0, 0);
    tpack_k<<<dim3(H_/32, CO_/32, 1), dim3(32, 8)>>>(W_v, WvTp, WvTph, CO_, H_, 0, 0);

    // G1: T1 = Qt^T·WqT  [NQ,512] K=H   (fp32 + packed)
    gemm_fp16x2<3><<<dim3(4, NQ_/128, B_), 256, SMEM_MMA>>>(Qtp, Qtph, NQ_, PQT, WqTp, WqTph, 0,
                                                            T1, sNC, T1p, T1ph, PNC, H_, 1.f, S);
    // G2: T2 = V^T·WvT   [NV,512] K=H   (fp32 + packed)
    gemm_fp16x2<3><<<dim3(4, NV_/128, B_), 256, SMEM_MMA>>>(Vp, Vph, NV_, PV, WvTp, WvTph, 0,
                                                            T2, sNC, T2p, T2ph, PNC, H_, 1.f, S);
    // G3: PvT = Q^T·T1   [H,512] K=NQ   (packed only; acc*16*(1/16) = acc)
    gemm_fp16x2<2><<<dim3(4, H_/128, B_), 256, SMEM_MMA>>>(Qp, Qph, H_, PQ, T1p, T1ph, PNC,
                                                           nullptr, 0, PvTp, PvTph, PHC, NQ_, R16, 1.f);
    // G4: RvT = Wb^T·PvT [H,512] K=H    (packed only)
    gemm_fp16x2<2><<<dim3(4, H_/128, B_), 256, SMEM_MMA>>>(Wbp, Wbph, H_, 0, PvTp, PvTph, PHC,
                                                           nullptr, 0, RvTp, RvTph, PHC, H_, R16, 1.f);
    // G5: MvT = V^T·RvT  [NV,512] K=H   (fp32 only)
    gemm_fp16x2<1><<<dim3(4, NV_/128, B_), 256, SMEM_MMA>>>(Vp, Vph, NV_, PV, RvTp, RvTph, PHC,
                                                            MvT, sNC, nullptr, nullptr, 0, H_, R16, 0.f);
    // G6: PqT = Vt^T·T2  [H,512] K=NV   (packed only; reuse PvT buffers)
    gemm_fp16x2<2><<<dim3(4, H_/128, B_), 256, SMEM_MMA>>>(Vtp, Vtph, H_, PVT, T2p, T2ph, PNC,
                                                           nullptr, 0, PvTp, PvTph, PHC, NV_, R16, 1.f);
    // G7: RqT = Wbt^T·PqT [H,512] K=H   (packed only; reuse RvT buffers)
    gemm_fp16x2<2><<<dim3(4, H_/128, B_), 256, SMEM_MMA>>>(Wbtp, Wbtph, H_, 0, PvTp, PvTph, PHC,
                                                           nullptr, 0, RvTp, RvTph, PHC, H_, R16, 1.f);
    // G8: MqT = Qt^T·RqT [NQ,512] K=H   (fp32 only)
    gemm_fp16x2<1><<<dim3(4, NQ_/128, B_), 256, SMEM_MMA>>>(Qtp, Qtph, NQ_, PQT, RvTp, RvTph, PHC,
                                                            MqT, sNC, nullptr, nullptr, 0, H_, R16, 0.f);

    logits_t<<<dim3(NV_/8, B_), 256>>>(T2, MvT, w_hv, logv, NV_);
    logits_t<<<dim3(NQ_/8, B_), 256>>>(T1, MqT, w_hq, logq, NQ_);

    float* out_av = out;
    float* out_aq = out + (size_t)B_ * NV_;
    float* out_v  = out + (size_t)B_ * (NV_ + NQ_);
    float* out_q  = out_v + (size_t)B_ * H_;

    softmax_kernel<<<B_, 256>>>(logv, out_av, NV_);
    softmax_kernel<<<B_, 256>>>(logq, out_aq, NQ_);

    wdot_kernel<<<dim3(H_/8, B_), 256>>>(out_av, V, out_v, NV_);
    aq_Q_partial<<<dim3(16, B_), 1024>>>(out_aq, Q, part);
    aq_Q_reduce<<<B_, 1024>>>(part, out_q);
}

// round 12
// speedup vs baseline: 2.0387x; 1.0728x over previous
#include <cuda_runtime.h>
#include <cuda_fp16.h>
#include <math.h>
#include <stdint.h>

constexpr int B_  = 16;
constexpr int H_  = 1024;
constexpr int CO_ = 512;
constexpr int NV_ = 2048;
constexpr int NQ_ = 2048;

// packed (uint32 = 2 fp16) operand sizes, per-batch counts
constexpr size_t PQ  = (size_t)(NQ_/2) * H_;    // Qp  [NQ/2][H]
constexpr size_t PQT = (size_t)(H_/2) * NQ_;    // Qtp [H/2][NQ]
constexpr size_t PV  = (size_t)(H_/2) * NV_;    // Vp  [H/2][NV]
constexpr size_t PVT = (size_t)(NV_/2) * H_;    // Vtp [NV/2][H]
constexpr size_t PW  = (size_t)(H_/2) * H_;
constexpr size_t PWC = (size_t)(H_/2) * CO_;
constexpr size_t PNC = (size_t)(NQ_/2) * CO_;
constexpr size_t PHC = (size_t)(H_/2) * CO_;

__device__ uint32_t g_Qp  [PQ  * B_], g_Qph [PQ  * B_];
__device__ uint32_t g_Qtp [PQT * B_], g_Qtph[PQT * B_];
__device__ uint32_t g_Vp  [PV  * B_], g_Vph [PV  * B_];
__device__ uint32_t g_Vtp [PVT * B_], g_Vtph[PVT * B_];
__device__ uint32_t g_Wbp [PW], g_Wbph[PW], g_Wbtp[PW], g_Wbtph[PW];
__device__ uint32_t g_WqTp[PWC], g_WqTph[PWC], g_WvTp[PWC], g_WvTph[PWC];
__device__ uint32_t g_T1p [PNC * B_], g_T1ph[PNC * B_];
__device__ uint32_t g_T2p [PNC * B_], g_T2ph[PNC * B_];
__device__ uint32_t g_PvTp[PHC * B_], g_PvTph[PHC * B_];
__device__ uint32_t g_PqTp[PHC * B_], g_PqTph[PHC * B_];
__device__ uint32_t g_RvTp[PHC * B_], g_RvTph[PHC * B_];
__device__ uint32_t g_RqTp[PHC * B_], g_RqTph[PHC * B_];

__device__ float g_T1 [(size_t)B_ * NQ_ * CO_];
__device__ float g_T2 [(size_t)B_ * NV_ * CO_];
__device__ float g_MvT[(size_t)B_ * NV_ * CO_];
__device__ float g_MqT[(size_t)B_ * NQ_ * CO_];
__device__ float g_logv[(size_t)B_ * NV_], g_logq[(size_t)B_ * NQ_];
__device__ float g_part[(size_t)B_ * 16 * H_];

__device__ __forceinline__ uint32_t smem_u32(const void* p) {
    uint32_t a;
    asm("{ .reg .u64 t; cvta.to.shared.u64 t, %1; cvt.u32.u64 %0, t; }" : "=r"(a) : "l"(p));
    return a;
}
#define CPA16(dst, src) \
    asm volatile("cp.async.cg.shared.global [%0], [%1], 16;" :: "r"(dst), "l"(src))
#define CP_COMMIT() asm volatile("cp.async.commit_group;" ::: "memory")
#define CP_WAIT1()  asm volatile("cp.async.wait_group 1;" ::: "memory")

__device__ __forceinline__ void pack2(float x0, float x1, uint32_t& u0, uint32_t& u1) {
    __half a0 = __float2half_rn(x0), a1 = __float2half_rn(x1);
    float r0 = x0 - __half2float(a0), r1 = x1 - __half2float(a1);
    __half b0 = __float2half_rn(r0), b1 = __float2half_rn(r1);
    u0 = (uint32_t)__half_as_ushort(a0) | ((uint32_t)__half_as_ushort(a1) << 16);
    u1 = (uint32_t)__half_as_ushort(b0) | ((uint32_t)__half_as_ushort(b1) << 16);
}
__device__ __forceinline__ void mma16(float* c, const uint32_t* a, const uint32_t* b) {
    asm volatile(
        "mma.sync.aligned.m16n8k16.row.col.f32.f16.f16.f32 "
        "{%0,%1,%2,%3}, {%4,%5,%6,%7}, {%8,%9}, {%0,%1,%2,%3};"
        : "+f"(c[0]), "+f"(c[1]), "+f"(c[2]), "+f"(c[3])
        : "r"(a[0]), "r"(a[1]), "r"(a[2]), "r"(a[3]), "r"(b[0]), "r"(b[1]));
}

// ---------------------------------------------------------------------------
// Paired GEMM: two same-shape C=A^T*B problems in one launch.
// grid = (4, M/128, 2*B_): z<16 -> set0 (chain A), z>=16 -> set1 (chain B).
// Everything else identical to the R11 kernel (block 128x128, 8 warps 64x32,
// K-slab 32, 3-stage cp.async, SROW=136 conflict-free).
// EPI bit0: fp32 C (acc*outScale). EPI bit1: packed hi/lo (acc*packScale).
// ---------------------------------------------------------------------------
constexpr int SROW = 136;
constexpr int TILE_U = 16 * SROW;
constexpr int STG_U = 4 * TILE_U;
constexpr int SMEM_MMA = 3 * STG_U * 4;    // 104448 B

template <int EPI>
__global__ __launch_bounds__(256, 2)
void gemm_pair(const uint32_t* __restrict__ Ah0, const uint32_t* __restrict__ Al0,
               const uint32_t* __restrict__ Bh0, const uint32_t* __restrict__ Bl0,
               const uint32_t* __restrict__ Ah1, const uint32_t* __restrict__ Al1,
               const uint32_t* __restrict__ Bh1, const uint32_t* __restrict__ Bl1,
               int lda, size_t sA, size_t sB,
               float* __restrict__ C0, float* __restrict__ C1, size_t sC,
               uint32_t* __restrict__ Ph0, uint32_t* __restrict__ Pl0,
               uint32_t* __restrict__ Ph1, uint32_t* __restrict__ Pl1, size_t sP,
               int K, float outScale, float packScale)
{
    extern __shared__ __align__(16) uint32_t sm[];
    const int tid = threadIdx.x;
    const int bx = blockIdx.x, by = blockIdx.y;
    const int zraw = blockIdx.z;
    const bool sec = (zraw >= B_);
    const int bz = sec ? zraw - B_ : zraw;

    const uint32_t* Ah = sec ? Ah1 : Ah0;
    const uint32_t* Al = sec ? Al1 : Al0;
    const uint32_t* Bh = sec ? Bh1 : Bh0;
    const uint32_t* Bl = sec ? Bl1 : Bl0;
    float* C = sec ? C1 : C0;
    uint32_t* Ph = sec ? Ph1 : Ph0;
    uint32_t* Pl = sec ? Pl1 : Pl0;

    const uint32_t* gAh = Ah + (size_t)bz * sA + by * 128;
    const uint32_t* gAl = Al + (size_t)bz * sA + by * 128;
    const uint32_t* gBh = Bh + (size_t)bz * sB + bx * 128;
    const uint32_t* gBl = Bl + (size_t)bz * sB + bx * 128;

    const int lane = tid & 31, w = tid >> 5;
    const int g = lane >> 2, t = lane & 3;
    const int rbase = (w & 1) * 64;
    const int cbase = (w >> 1) * 32;

    const uint32_t smb = smem_u32(sm);
    const int srow = tid >> 4;
    const int scol = (tid & 15) * 8;

    float c[4][4][4];
#pragma unroll
    for (int i = 0; i < 4; ++i)
#pragma unroll
        for (int j = 0; j < 4; ++j)
#pragma unroll
            for (int k = 0; k < 4; ++k) c[i][j][k] = 0.f;

    const int T = K >> 5;
    const uint32_t doff = (uint32_t)(srow * SROW + scol) * 4;

#define STAGE_LOADS(sidx, kp0) do {                                             \
    const uint32_t base_ = smb + (uint32_t)(sidx) * (STG_U * 4);                \
    const size_t kr_ = (size_t)((kp0) + srow);                                  \
    CPA16(base_ + doff,                    gAh + kr_ * lda + scol);             \
    CPA16(base_ + doff + 16,               gAh + kr_ * lda + scol + 4);         \
    CPA16(base_ + TILE_U*4 + doff,         gAl + kr_ * lda + scol);             \
    CPA16(base_ + TILE_U*4 + doff + 16,    gAl + kr_ * lda + scol + 4);         \
    CPA16(base_ + 2*TILE_U*4 + doff,       gBh + kr_ * 512 + scol);             \
    CPA16(base_ + 2*TILE_U*4 + doff + 16,  gBh + kr_ * 512 + scol + 4);         \
    CPA16(base_ + 3*TILE_U*4 + doff,       gBl + kr_ * 512 + scol);             \
    CPA16(base_ + 3*TILE_U*4 + doff + 16,  gBl + kr_ * 512 + scol + 4);         \
} while (0)

#pragma unroll
    for (int s = 0; s < 3; ++s) {
        STAGE_LOADS(s, s * 16);
        CP_COMMIT();
    }

    int buf = 0;
    for (int tt = 0; tt < T; ++tt) {
        CP_WAIT1();
        __syncthreads();

        const uint32_t* Ahs = sm + buf * STG_U;
        const uint32_t* Als = Ahs + TILE_U;
        const uint32_t* Bhs = Als + TILE_U;
        const uint32_t* Bls = Bhs + TILE_U;
#pragma unroll
        for (int ks = 0; ks < 2; ++ks) {
            const int kr = ks * 8 + t;
            const uint32_t* aph = Ahs + kr * SROW;
            const uint32_t* apl = Als + kr * SROW;
            const uint32_t* bph = Bhs + kr * SROW;
            const uint32_t* bpl = Bls + kr * SROW;
            uint32_t ah[4][4], al[4][4], bh[4][2], bl[4][2];
#pragma unroll
            for (int i = 0; i < 4; ++i) {
                const int m = rbase + i * 16 + g;
                ah[i][0] = aph[m];            al[i][0] = apl[m];
                ah[i][1] = aph[m + 8];        al[i][1] = apl[m + 8];
                ah[i][2] = aph[4*SROW + m];   al[i][2] = apl[4*SROW + m];
                ah[i][3] = aph[4*SROW + m+8]; al[i][3] = apl[4*SROW + m+8];
            }
#pragma unroll
            for (int j = 0; j < 4; ++j) {
                const int n = cbase + j * 8 + g;
                bh[j][0] = bph[n];            bl[j][0] = bpl[n];
                bh[j][1] = bph[4*SROW + n];   bl[j][1] = bpl[4*SROW + n];
            }
#pragma unroll
            for (int i = 0; i < 4; ++i)
#pragma unroll
                for (int j = 0; j < 4; ++j) {
                    mma16(c[i][j], ah[i], bl[j]);
                    mma16(c[i][j], al[i], bh[j]);
                    mma16(c[i][j], ah[i], bh[j]);
                }
        }
        __syncthreads();

        if (tt + 3 < T) STAGE_LOADS(buf, (tt + 3) * 16);
        CP_COMMIT();
        buf = (buf == 2) ? 0 : buf + 1;
    }
#undef STAGE_LOADS

    if (EPI & 1) {
        const size_t coff = (size_t)bz * sC + (size_t)(by * 128) * 512 + bx * 128;
#pragma unroll
        for (int i = 0; i < 4; ++i) {
            const int r0 = rbase + i * 16 + g;
#pragma unroll
            for (int j = 0; j < 4; ++j) {
                const int cc = cbase + j * 8 + 2 * t;
                *reinterpret_cast<float2*>(C + coff + (size_t)r0 * 512 + cc) =
                    make_float2(c[i][j][0] * outScale, c[i][j][1] * outScale);
                *reinterpret_cast<float2*>(C + coff + (size_t)(r0 + 8) * 512 + cc) =
                    make_float2(c[i][j][2] * outScale, c[i][j][3] * outScale);
            }
        }
    }
    if (EPI & 2) {
        float* cs = reinterpret_cast<float*>(sm);
#pragma unroll
        for (int i = 0; i < 4; ++i) {
            const int r0 = rbase + i * 16 + g;
#pragma unroll
            for (int j = 0; j < 4; ++j) {
                const int cc = cbase + j * 8 + 2 * t;
                *reinterpret_cast<float2*>(cs + r0 * 132 + cc) =
                    make_float2(c[i][j][0], c[i][j][1]);
                *reinterpret_cast<float2*>(cs + (r0 + 8) * 132 + cc) =
                    make_float2(c[i][j][2], c[i][j][3]);
            }
        }
        __syncthreads();
        const size_t poff = (size_t)bz * sP + (size_t)(by * 64) * 512 + bx * 128;
#pragma unroll 4
        for (int it = 0; it < 32; ++it) {
            const int idx = it * 256 + tid;
            const int kp = idx >> 7, cc2 = idx & 127;
            const float x0 = cs[(2 * kp) * 132 + cc2] * packScale;
            const float x1 = cs[(2 * kp + 1) * 132 + cc2] * packScale;
            uint32_t u0, u1;
            pack2(x0, x1, u0, u1);
            Ph[poff + (size_t)kp * 512 + cc2] = u0;
            Pl[poff + (size_t)kp * 512 + cc2] = u1;
        }
    }
}

// --- dual pack: src[R][C] -> straight [R/2][C] AND transposed [C/2][R] ----
__global__ void dual_pack_k(const float* __restrict__ src,
                            uint32_t* __restrict__ sh0, uint32_t* __restrict__ sh1,
                            uint32_t* __restrict__ th0, uint32_t* __restrict__ th1,
                            int R, int C, size_t sS, size_t sSd, size_t sTd)
{
    __shared__ float tile[32][33];
    const size_t so = (size_t)blockIdx.z * sS;
    const int x0 = blockIdx.x * 32, y0 = blockIdx.y * 32;
    for (int j = threadIdx.y; j < 32; j += 8)
        tile[j][threadIdx.x] = src[so + (size_t)(y0 + j) * C + x0 + threadIdx.x];
    __syncthreads();
    const int tx = threadIdx.x;
    for (int kpl = threadIdx.y; kpl < 16; kpl += 8) {
        uint32_t u0, u1;
        pack2(tile[2 * kpl][tx], tile[2 * kpl + 1][tx], u0, u1);
        size_t o = (size_t)blockIdx.z * sSd + (size_t)(y0 / 2 + kpl) * C + x0 + tx;
        sh0[o] = u0; sh1[o] = u1;
        pack2(tile[tx][2 * kpl], tile[tx][2 * kpl + 1], u0, u1);
        o = (size_t)blockIdx.z * sTd + (size_t)(x0 / 2 + kpl) * R + y0 + tx;
        th0[o] = u0; th1[o] = u1;
    }
}

// --- transpose pack only: src[R][C] -> [C/2][R] ---------------------------
__global__ void tpack_k(const float* __restrict__ src, uint32_t* __restrict__ h0,
                        uint32_t* __restrict__ h1, int R, int C, size_t sS, size_t sD)
{
    __shared__ float tile[32][33];
    const size_t so = (size_t)blockIdx.z * sS;
    const int x0 = blockIdx.x * 32, y0 = blockIdx.y * 32;
    for (int j = threadIdx.y; j < 32; j += 8)
        tile[j][threadIdx.x] = src[so + (size_t)(y0 + j) * C + x0 + threadIdx.x];
    __syncthreads();
    const int tx = threadIdx.x;
    for (int kpl = threadIdx.y; kpl < 16; kpl += 8) {
        uint32_t u0, u1;
        pack2(tile[tx][2 * kpl], tile[tx][2 * kpl + 1], u0, u1);
        const size_t o = (size_t)blockIdx.z * sD + (size_t)(x0 / 2 + kpl) * R + y0 + tx;
        h0[o] = u0; h1[o] = u1;
    }
}

// ---- merged logits: z=0 -> (X0,Y0,w0,lg0), z=1 -> (X1,Y1,w1,lg1) ---------
__global__ void logits_t2(const float* __restrict__ X0, const float* __restrict__ Y0,
                          const float* __restrict__ w0, float* __restrict__ lg0,
                          const float* __restrict__ X1, const float* __restrict__ Y1,
                          const float* __restrict__ w1, float* __restrict__ lg1,
                          int Ncol)
{
    const bool sec = (blockIdx.z != 0);
    const float* X = sec ? X1 : X0;
    const float* Y = sec ? Y1 : Y0;
    const float* w = sec ? w1 : w0;
    float* lg = sec ? lg1 : lg0;
    const int b = blockIdx.y;
    const int n = blockIdx.x * 8 + (threadIdx.x >> 5);
    const int lane = threadIdx.x & 31;
    const float* xp = X + ((size_t)b * Ncol + n) * CO_;
    const float* yp = Y + ((size_t)b * Ncol + n) * CO_;
    float acc = 0.f;
#pragma unroll 4
    for (int c = lane; c < CO_; c += 32)
        acc += w[c] * tanhf(xp[c] + yp[c]);
#pragma unroll
    for (int off = 16; off > 0; off >>= 1)
        acc += __shfl_down_sync(0xffffffffu, acc, off);
    if (lane == 0) lg[(size_t)b * Ncol + n] = acc;
}

// ---- merged softmax: blocks 0..15 -> (lg0,out0), 16..31 -> (lg1,out1) ----
__global__ void softmax2(const float* __restrict__ lg0, float* __restrict__ o0,
                         const float* __restrict__ lg1, float* __restrict__ o1,
                         int Ncol)
{
    __shared__ float buf[2048];
    __shared__ float red[256];
    const bool sec = (blockIdx.x >= B_);
    const int b = sec ? blockIdx.x - B_ : blockIdx.x;
    const float* x = (sec ? lg1 : lg0) + (size_t)b * Ncol;
    float* outp = (sec ? o1 : o0) + (size_t)b * Ncol;
    const int tid = threadIdx.x;
    float mx = -INFINITY;
    for (int i = tid; i < Ncol; i += 256) { float v = x[i]; buf[i] = v; mx = fmaxf(mx, v); }
    red[tid] = mx; __syncthreads();
    for (int s = 128; s > 0; s >>= 1) { if (tid < s) red[tid] = fmaxf(red[tid], red[tid + s]); __syncthreads(); }
    mx = red[0]; __syncthreads();
    float sm = 0.f;
    for (int i = tid; i < Ncol; i += 256) { float e = expf(buf[i] - mx); buf[i] = e; sm += e; }
    red[tid] = sm; __syncthreads();
    for (int s = 128; s > 0; s >>= 1) { if (tid < s) red[tid] += red[tid + s]; __syncthreads(); }
    const float inv = 1.f / red[0];
    for (int i = tid; i < Ncol; i += 256) outp[i] = buf[i] * inv;
}

__global__ void wdot_kernel(const float* __restrict__ a, const float* __restrict__ X,
                            float* __restrict__ outv, int Ncol)
{
    const int b = blockIdx.y;
    const int h = blockIdx.x * 8 + (threadIdx.x >> 5);
    const int lane = threadIdx.x & 31;
    const float* row = X + ((size_t)b * H_ + h) * Ncol;
    const float* av = a + (size_t)b * Ncol;
    float acc = 0.f;
    for (int i = lane; i < Ncol; i += 32) acc += av[i] * row[i];
#pragma unroll
    for (int off = 16; off > 0; off >>= 1) acc += __shfl_down_sync(0xffffffffu, acc, off);
    if (lane == 0) outv[(size_t)b * H_ + h] = acc;
}

__global__ void aq_Q_partial(const float* __restrict__ a, const float* __restrict__ Q,
                             float* __restrict__ part)
{
    const int b = blockIdx.y, j = blockIdx.x;
    const int h = threadIdx.x;
    const float* aq = a + (size_t)b * NQ_;
    float acc = 0.f;
    const int q0 = j * (NQ_ / 16);
    for (int q = q0; q < q0 + NQ_ / 16; ++q)
        acc += aq[q] * Q[((size_t)b * NQ_ + q) * H_ + h];
    part[((size_t)b * 16 + j) * H_ + h] = acc;
}
__global__ void aq_Q_reduce(const float* __restrict__ part, float* __restrict__ outq)
{
    const int b = blockIdx.x;
    const int h = threadIdx.x;
    float acc = 0.f;
#pragma unroll
    for (int j = 0; j < 16; ++j)
        acc += part[((size_t)b * 16 + j) * H_ + h];
    outq[(size_t)b * H_ + h] = acc;
}

// ---------------------------------------------------------------------------
extern "C" void kernel_launch(void* const* d_in, const int* in_sizes, int n_in,
                              void* d_out, int out_size)
{
    const float* V    = (const float*)d_in[0];  // [B, H, NV]
    const float* Q    = (const float*)d_in[1];  // [B, NQ, H]
    const float* W_b  = (const float*)d_in[2];  // [H, H]
    const float* W_v  = (const float*)d_in[3];  // [CO, H]
    const float* W_q  = (const float*)d_in[4];  // [CO, H]
    const float* w_hv = (const float*)d_in[5];
    const float* w_hq = (const float*)d_in[6];
    float* out = (float*)d_out;

#define USYM(p, s) uint32_t* p; cudaGetSymbolAddress((void**)&p, s)
#define FSYM(p, s) float* p;    cudaGetSymbolAddress((void**)&p, s)
    USYM(Qp, g_Qp);     USYM(Qph, g_Qph);
    USYM(Qtp, g_Qtp);   USYM(Qtph, g_Qtph);
    USYM(Vp, g_Vp);     USYM(Vph, g_Vph);
    USYM(Vtp, g_Vtp);   USYM(Vtph, g_Vtph);
    USYM(Wbp, g_Wbp);   USYM(Wbph, g_Wbph);
    USYM(Wbtp, g_Wbtp); USYM(Wbtph, g_Wbtph);
    USYM(WqTp, g_WqTp); USYM(WqTph, g_WqTph);
    USYM(WvTp, g_WvTp); USYM(WvTph, g_WvTph);
    USYM(T1p, g_T1p);   USYM(T1ph, g_T1ph);
    USYM(T2p, g_T2p);   USYM(T2ph, g_T2ph);
    USYM(PvTp, g_PvTp); USYM(PvTph, g_PvTph);
    USYM(PqTp, g_PqTp); USYM(PqTph, g_PqTph);
    USYM(RvTp, g_RvTp); USYM(RvTph, g_RvTph);
    USYM(RqTp, g_RqTp); USYM(RqTph, g_RqTph);
    FSYM(T1, g_T1);   FSYM(T2, g_T2);
    FSYM(MvT, g_MvT); FSYM(MqT, g_MqT);
    FSYM(logv, g_logv); FSYM(logq, g_logq); FSYM(part, g_part);
#undef USYM
#undef FSYM

    cudaFuncSetAttribute(gemm_pair<1>, cudaFuncAttributeMaxDynamicSharedMemorySize, SMEM_MMA);
    cudaFuncSetAttribute(gemm_pair<2>, cudaFuncAttributeMaxDynamicSharedMemorySize, SMEM_MMA);
    cudaFuncSetAttribute(gemm_pair<3>, cudaFuncAttributeMaxDynamicSharedMemorySize, SMEM_MMA);

    const size_t sQ = (size_t)NQ_ * H_, sV = (size_t)H_ * NV_;
    const size_t sNC = (size_t)NQ_ * CO_;
    const float S = 0.0625f;    // 1/16 intermediate pack scale
    const float R16 = 16.0f;

    // pre-pass
    dual_pack_k<<<dim3(H_/32, NQ_/32, B_), dim3(32, 8)>>>(Q, Qp, Qph, Qtp, Qtph, NQ_, H_, sQ, PQ, PQT);
    dual_pack_k<<<dim3(NV_/32, H_/32, B_), dim3(32, 8)>>>(V, Vp, Vph, Vtp, Vtph, H_, NV_, sV, PV, PVT);
    dual_pack_k<<<dim3(H_/32, H_/32, 1),  dim3(32, 8)>>>(W_b, Wbp, Wbph, Wbtp, Wbtph, H_, H_, 0, 0, 0);
    tpack_k<<<dim3(H_/32, CO_/32, 1), dim3(32, 8)>>>(W_q, WqTp, WqTph, CO_, H_, 0, 0);
    tpack_k<<<dim3(H_/32, CO_/32, 1), dim3(32, 8)>>>(W_v, WvTp, WvTph, CO_, H_, 0, 0);

    // pair1: G1 T1 = Qt^T·WqT  |  G2 T2 = V^T·WvT     [2048,512] K=1024
    gemm_pair<3><<<dim3(4, NQ_/128, 2*B_), 256, SMEM_MMA>>>(
        Qtp, Qtph, WqTp, WqTph,   Vp, Vph, WvTp, WvTph,
        2048, PQT, 0,  T1, T2, sNC,  T1p, T1ph, T2p, T2ph, PNC,  H_, 1.f, S);
    // pair2: G3 PvT = Q^T·T1   |  G6 PqT = Vt^T·T2    [1024,512] K=2048
    gemm_pair<2><<<dim3(4, H_/128, 2*B_), 256, SMEM_MMA>>>(
        Qp, Qph, T1p, T1ph,   Vtp, Vtph, T2p, T2ph,
        1024, PQ, PNC,  nullptr, nullptr, 0,  PvTp, PvTph, PqTp, PqTph, PHC,  NQ_, R16, 1.f);
    // pair3: G4 RvT = Wb^T·PvT |  G7 RqT = Wbt^T·PqT  [1024,512] K=1024
    gemm_pair<2><<<dim3(4, H_/128, 2*B_), 256, SMEM_MMA>>>(
        Wbp, Wbph, PvTp, PvTph,   Wbtp, Wbtph, PqTp, PqTph,
        1024, 0, PHC,  nullptr, nullptr, 0,  RvTp, RvTph, RqTp, RqTph, PHC,  H_, R16, 1.f);
    // pair4: G5 MvT = V^T·RvT  |  G8 MqT = Qt^T·RqT   [2048,512] K=1024
    gemm_pair<1><<<dim3(4, NV_/128, 2*B_), 256, SMEM_MMA>>>(
        Vp, Vph, RvTp, RvTph,   Qtp, Qtph, RqTp, RqTph,
        2048, PV, PHC,  MvT, MqT, sNC,  nullptr, nullptr, nullptr, nullptr, 0,  H_, R16, 0.f);

    // merged logits + softmax
    logits_t2<<<dim3(NV_/8, B_, 2), 256>>>(T2, MvT, w_hv, logv, T1, MqT, w_hq, logq, NV_);

    float* out_av = out;
    float* out_aq = out + (size_t)B_ * NV_;
    float* out_v  = out + (size_t)B_ * (NV_ + NQ_);
    float* out_q  = out_v + (size_t)B_ * H_;

    softmax2<<<2 * B_, 256>>>(logv, out_av, logq, out_aq, NV_);

    wdot_kernel<<<dim3(H_/8, B_), 256>>>(out_av, V, out_v, NV_);
    aq_Q_partial<<<dim3(16, B_), 1024>>>(out_aq, Q, part);
    aq_Q_reduce<<<B_, 1024>>>(part, out_q);
}